// round 1
// baseline (speedup 1.0000x reference)
#include <cuda_runtime.h>
#include <cuda_bf16.h>
#include <math.h>

// Problem constants
#define NB 64
#define NN 256
#define NS 2000
#define KK 100
#define BIL 4
#define NITERS 200

// Device scratch (static device globals are allowed; no runtime allocation)
__device__ float g_L[NB * NN * NN];    // L row-major: L[b][m][n]
__device__ float g_LT[NB * NN * NN];   // LT[b][n'][n] = L[b][n][n']
__device__ float g_w[NB * NN];
__device__ float g_u[NB * NN];
__device__ float g_muw[NB];
__device__ float g_losses[NB * NS];

// ---------------------------------------------------------------------------
// Cholesky: one block per batch, packed lower triangle in dynamic smem.
// ---------------------------------------------------------------------------
__device__ __forceinline__ int tri_row_of(int idx) {
    float f = sqrtf(8.0f * (float)idx + 1.0f);
    int i = (int)((f - 1.0f) * 0.5f);
    while ((i + 1) * (i + 2) / 2 <= idx) ++i;
    while (i * (i + 1) / 2 > idx) --i;
    return i;
}

extern "C" __global__ void __launch_bounds__(256)
chol_kernel(const float* __restrict__ sigma) {
    extern __shared__ float sm[];   // 256*257/2 = 32896 floats
    const int b = blockIdx.x;
    const int tid = threadIdx.x;
    const float* A = sigma + (size_t)b * NN * NN;

    for (int idx = tid; idx < 32896; idx += 256) {
        int i = tri_row_of(idx);
        int j = idx - i * (i + 1) / 2;
        float v = A[i * NN + j];
        if (i == j) v += 1e-4f;   // jitter
        sm[idx] = v;
    }
    __syncthreads();

    __shared__ float sdiag;
    float acc = 0.0f;  // running sum of squares of own row (thread tid == row tid)
    const int base_i = tid * (tid + 1) / 2;

    for (int j = 0; j < NN; ++j) {
        if (tid == j) {
            float d = sm[j * (j + 1) / 2 + j] - acc;
            sdiag = sqrtf(fmaxf(d, 1e-20f));
            sm[j * (j + 1) / 2 + j] = sdiag;
        }
        __syncthreads();
        float dinv = 1.0f / sdiag;
        if (tid > j) {
            const int base_j = j * (j + 1) / 2;
            float s = sm[base_i + j];
            int k = 0;
            for (; k + 4 <= j; k += 4) {
                s -= sm[base_i + k]     * sm[base_j + k];
                s -= sm[base_i + k + 1] * sm[base_j + k + 1];
                s -= sm[base_i + k + 2] * sm[base_j + k + 2];
                s -= sm[base_i + k + 3] * sm[base_j + k + 3];
            }
            for (; k < j; ++k) s -= sm[base_i + k] * sm[base_j + k];
            float lij = s * dinv;
            sm[base_i + j] = lij;
            acc += lij * lij;
        }
        __syncthreads();
    }

    // write L (row-major) and LT
    float* Lb  = g_L  + (size_t)b * NN * NN;
    float* LTb = g_LT + (size_t)b * NN * NN;
    for (int idx = tid; idx < NN * NN; idx += 256) {
        int i = idx >> 8, j = idx & 255;
        Lb[idx] = (j <= i) ? sm[i * (i + 1) / 2 + j] : 0.0f;
    }
    for (int idx = tid; idx < NN * NN; idx += 256) {
        int r = idx >> 8, c = idx & 255;   // LT[r][c] = L[c][r]
        LTb[idx] = (r <= c) ? sm[c * (c + 1) / 2 + r] : 0.0f;
    }
}

// ---------------------------------------------------------------------------
// Block-wide simplex projection (256 values, one per thread).
// Returns max(v - theta, 0) with theta from sorted-cumsum rule.
// ---------------------------------------------------------------------------
__device__ __forceinline__ float simplex_proj_block(
    float v, float z, int tid, float* sv, float* sc, int* srho, float* stheta)
{
    sv[tid] = v;
    __syncthreads();
    // bitonic sort descending
    for (int k = 2; k <= 256; k <<= 1) {
        for (int j = k >> 1; j > 0; j >>= 1) {
            int ixj = tid ^ j;
            if (ixj > tid) {
                float a = sv[tid], b2 = sv[ixj];
                bool desc = ((tid & k) == 0);
                bool dosw = desc ? (a < b2) : (a > b2);
                if (dosw) { sv[tid] = b2; sv[ixj] = a; }
            }
            __syncthreads();
        }
    }
    // inclusive cumsum
    sc[tid] = sv[tid];
    __syncthreads();
    for (int off = 1; off < 256; off <<= 1) {
        float t = (tid >= off) ? sc[tid - off] : 0.0f;
        __syncthreads();
        sc[tid] += t;
        __syncthreads();
    }
    float css = sc[tid] - z;
    bool cond = (sv[tid] - css / (float)(tid + 1)) > 0.0f;
    if (tid == 0) *srho = 0;
    __syncthreads();
    if (cond) atomicAdd(srho, 1);
    __syncthreads();
    if (tid == 0) {
        int rho = *srho;
        *stheta = (sc[rho - 1] - z) / (float)rho;
    }
    __syncthreads();
    return fmaxf(v - *stheta, 0.0f);
}

// Deterministic block reduce (tree) into sc[0]
__device__ __forceinline__ void block_reduce(float* sc, int tid) {
    for (int off = 128; off > 0; off >>= 1) {
        if (tid < off) sc[tid] += sc[tid + off];
        __syncthreads();
    }
}

// Compute u = L^T w and muw (given sw holds w, sc scratch)
__device__ __forceinline__ void compute_u_muw(
    int b, int tid, const float* __restrict__ mu, float lamscale,
    float* sw, float* sc)
{
    float pw = sw[tid];
    float mue = mu[b * NN + tid] * lamscale;
    sc[tid] = mue * pw;
    __syncthreads();
    block_reduce(sc, tid);
    if (tid == 0) g_muw[b] = sc[0];

    const float* Lb = g_L + (size_t)b * NN * NN;
    float acc = 0.0f;
    #pragma unroll 8
    for (int m = 0; m < NN; ++m) acc += Lb[m * NN + tid] * sw[m];
    g_u[b * NN + tid] = acc;
}

// ---------------------------------------------------------------------------
// Init kernel: w0 = proj(1/n), then u, muw.
// ---------------------------------------------------------------------------
extern "C" __global__ void __launch_bounds__(256)
init_kernel(const float* __restrict__ mu,
            const int* __restrict__ p_crisis, const int* __restrict__ p_lambda)
{
    __shared__ float sf1[256], sf2[256], sw[256];
    __shared__ int s_rho;
    __shared__ float s_theta;

    const int b = blockIdx.x;
    const int tid = threadIdx.x;
    const float crisis = (float)(*p_crisis);
    const int lam = *p_lambda;
    const float lamscale = (lam > 0) ? (1.0f + 1.0f / fmaxf((float)lam, 0.1f)) : 1.0f;

    const float fl = (tid == BIL) ? 0.5f * crisis : 0.0f;
    const float z = 1.0f - 0.5f * crisis;
    float v = (1.0f / (float)NN) - fl;
    float pw = simplex_proj_block(v, z, tid, sf1, sf2, &s_rho, &s_theta) + fl;
    g_w[b * NN + tid] = pw;
    sw[tid] = pw;
    __syncthreads();
    compute_u_muw(b, tid, mu, lamscale, sw, sf2);
}

// ---------------------------------------------------------------------------
// Losses: one warp per scenario. losses[b,s] = -(muw + eps[b,s,:].u[b,:])
// eps streamed with evict-first so L/LT stay L2-resident.
// ---------------------------------------------------------------------------
extern "C" __global__ void __launch_bounds__(256)
loss_kernel(const float* __restrict__ eps)
{
    __shared__ float4 su4[64];
    __shared__ float smuw;
    const int blk = blockIdx.x;
    const int b = blk / (NS / 8);
    const int s0 = (blk % (NS / 8)) * 8;
    const int tid = threadIdx.x;

    if (tid < 64) su4[tid] = ((const float4*)(g_u + b * NN))[tid];
    if (tid == 0) smuw = g_muw[b];
    __syncthreads();

    const int warp = tid >> 5, lane = tid & 31;
    const int s = s0 + warp;
    const float4* ep = (const float4*)(eps + ((size_t)b * NS + s) * NN);
    float4 a = __ldcs(ep + lane);
    float4 c = __ldcs(ep + 32 + lane);
    float4 u0 = su4[lane];
    float4 u1 = su4[lane + 32];
    float dot = a.x * u0.x + a.y * u0.y + a.z * u0.z + a.w * u0.w
              + c.x * u1.x + c.y * u1.y + c.z * u1.z + c.w * u1.w;
    #pragma unroll
    for (int off = 16; off > 0; off >>= 1)
        dot += __shfl_down_sync(0xffffffffu, dot, off);
    if (lane == 0) g_losses[b * NS + s] = -(smuw + dot);
}

// ---------------------------------------------------------------------------
// Iteration kernel: per-batch top-K radix select + sparse subgradient +
// simplex projection + (u, muw) for the next iteration.
// ---------------------------------------------------------------------------
extern "C" __global__ void __launch_bounds__(256)
iter_kernel(const float* __restrict__ mu, const float* __restrict__ eps,
            const int* __restrict__ p_crisis, const int* __restrict__ p_lambda,
            int t, float* __restrict__ out)
{
    __shared__ unsigned skey[NS];
    __shared__ int ssel[NS];
    __shared__ int shist[256];
    __shared__ int sscan[256];
    __shared__ float sf1[256], sf2[256], svv[256], sw[256];
    __shared__ unsigned s_P;
    __shared__ int s_k, s_rho;
    __shared__ float s_theta;

    const int b = blockIdx.x;
    const int tid = threadIdx.x;

    // load losses -> monotone sortable keys
    for (int s = tid; s < NS; s += 256) {
        unsigned ub = __float_as_uint(g_losses[b * NS + s]);
        skey[s] = (ub & 0x80000000u) ? ~ub : (ub | 0x80000000u);
    }
    if (tid == 0) { s_P = 0u; s_k = KK; }
    __syncthreads();

    // 4-pass MSD radix select for K-th largest key
    #pragma unroll
    for (int p = 0; p < 4; ++p) {
        const int shift = 24 - 8 * p;
        shist[tid] = 0;
        __syncthreads();
        unsigned Pc = s_P;
        for (int s = tid; s < NS; s += 256) {
            unsigned key = skey[s];
            bool match = (p == 0) || ((key >> (shift + 8)) == (Pc >> (shift + 8)));
            if (match) atomicAdd(&shist[(key >> shift) & 255u], 1);
        }
        __syncthreads();
        sscan[tid] = shist[255 - tid];   // reversed for suffix counts
        __syncthreads();
        for (int off = 1; off < 256; off <<= 1) {
            int v = (tid >= off) ? sscan[tid - off] : 0;
            __syncthreads();
            sscan[tid] += v;
            __syncthreads();
        }
        int Cd  = sscan[tid];
        int Cd1 = (tid > 0) ? sscan[tid - 1] : 0;
        int kcur = s_k;
        unsigned Pcur = s_P;
        __syncthreads();
        if (Cd >= kcur && Cd1 < kcur) {
            int d = 255 - tid;
            s_P = Pcur | ((unsigned)d << shift);
            s_k = kcur - Cd1;
        }
        __syncthreads();
    }
    const unsigned T = s_P;

    // deterministic compaction of selected scenarios (key >= T)
    int mycnt = 0;
    for (int s = tid; s < NS; s += 256)
        if (skey[s] >= T) mycnt++;
    sscan[tid] = mycnt;
    __syncthreads();
    for (int off = 1; off < 256; off <<= 1) {
        int v = (tid >= off) ? sscan[tid - off] : 0;
        __syncthreads();
        sscan[tid] += v;
        __syncthreads();
    }
    const int total = sscan[255];
    int ofs = sscan[tid] - mycnt;
    for (int s = tid; s < NS; s += 256)
        if (skey[s] >= T) ssel[ofs++] = s;
    __syncthreads();

    const float coef = 1.0f / fmaxf((float)total, (float)KK);
    const float summ = (float)total * coef;

    // v[n] = coef * sum_{selected s} eps[b,s,n]   (sparse pass, ~5% of eps)
    const float* epsb = eps + (size_t)b * NS * NN;
    {
        float a0 = 0.f, a1 = 0.f, a2 = 0.f, a3 = 0.f;
        int i = 0;
        for (; i + 4 <= total; i += 4) {
            a0 += __ldg(&epsb[(size_t)ssel[i]     * NN + tid]);
            a1 += __ldg(&epsb[(size_t)ssel[i + 1] * NN + tid]);
            a2 += __ldg(&epsb[(size_t)ssel[i + 2] * NN + tid]);
            a3 += __ldg(&epsb[(size_t)ssel[i + 3] * NN + tid]);
        }
        for (; i < total; ++i) a0 += __ldg(&epsb[(size_t)ssel[i] * NN + tid]);
        svv[tid] = ((a0 + a1) + (a2 + a3)) * coef;
    }
    __syncthreads();

    // g[n] = -(summ*mu_eff[n] + sum_{n'} LT[n'][n]*v[n'])
    const int lam = *p_lambda;
    const float lamscale = (lam > 0) ? (1.0f + 1.0f / fmaxf((float)lam, 0.1f)) : 1.0f;
    const float mue = mu[b * NN + tid] * lamscale;
    const float* LTb = g_LT + (size_t)b * NN * NN;
    float lv = 0.0f;
    #pragma unroll 8
    for (int n = 0; n < NN; ++n) lv += LTb[n * NN + tid] * svv[n];
    const float gval = -(summ * mue + lv);

    // projected update
    const float crisis = (float)(*p_crisis);
    const float fl = (tid == BIL) ? 0.5f * crisis : 0.0f;
    const float z = 1.0f - 0.5f * crisis;
    const float lr = 0.5f / sqrtf((float)t + 1.0f);
    float wv = g_w[b * NN + tid] - lr * gval - fl;
    float pw = simplex_proj_block(wv, z, tid, sf1, sf2, &s_rho, &s_theta) + fl;
    g_w[b * NN + tid] = pw;
    sw[tid] = pw;
    __syncthreads();

    if (t == NITERS - 1) {
        // final clamp + renormalize
        float wc = fmaxf(pw, 0.0f);
        sf2[tid] = wc;
        __syncthreads();
        block_reduce(sf2, tid);
        out[b * NN + tid] = wc / (sf2[0] + 1e-8f);
    } else {
        compute_u_muw(b, tid, mu, lamscale, sw, sf2);
    }
}

// ---------------------------------------------------------------------------
extern "C" void kernel_launch(void* const* d_in, const int* in_sizes, int n_in,
                              void* d_out, int out_size)
{
    const float* mu     = (const float*)d_in[0];
    const float* sigma  = (const float*)d_in[1];
    const float* eps    = (const float*)d_in[2];
    const int*   crisis = (const int*)d_in[3];
    const int*   lambda = (const int*)d_in[4];
    float* out = (float*)d_out;

    cudaFuncSetAttribute(chol_kernel, cudaFuncAttributeMaxDynamicSharedMemorySize,
                         32896 * sizeof(float));

    chol_kernel<<<NB, 256, 32896 * sizeof(float)>>>(sigma);
    init_kernel<<<NB, 256>>>(mu, crisis, lambda);
    for (int t = 0; t < NITERS; ++t) {
        loss_kernel<<<NB * (NS / 8), 256>>>(eps);
        iter_kernel<<<NB, 256>>>(mu, eps, crisis, lambda, t, out);
    }
}

// round 2
// speedup vs baseline: 1.3257x; 1.3257x over previous
#include <cuda_runtime.h>
#include <cuda_fp16.h>
#include <cuda_bf16.h>
#include <math.h>

// Problem constants
#define NB 64
#define NN 256
#define NS 2000
#define KK 100
#define BIL 4
#define NITERS 200

// Device scratch
__device__ float g_L[NB * NN * NN];    // L row-major: L[b][m][n]
__device__ float g_LT[NB * NN * NN];   // LT[b][n'][n] = L[b][n][n']
__device__ float g_w[NB * NN];
__device__ float g_u[NB * NN];
__device__ float g_muw[NB];
__device__ float g_losses[NB * NS];
__device__ __align__(16) __half g_eps16[(size_t)NB * NS * NN];   // 65.5 MB, L2-resident

// ---------------------------------------------------------------------------
// eps fp32 -> fp16 conversion (once per launch)
// ---------------------------------------------------------------------------
extern "C" __global__ void __launch_bounds__(256)
conv_kernel(const float* __restrict__ eps)
{
    size_t i = (size_t)blockIdx.x * blockDim.x + threadIdx.x;   // one float4 each
    const size_t total4 = (size_t)NB * NS * NN / 4;
    if (i >= total4) return;
    float4 v = __ldcs(((const float4*)eps) + i);
    __half2* o = (__half2*)g_eps16;
    o[2 * i]     = __floats2half2_rn(v.x, v.y);
    o[2 * i + 1] = __floats2half2_rn(v.z, v.w);
}

// ---------------------------------------------------------------------------
// Cholesky: one block per batch, packed lower triangle in dynamic smem.
// ---------------------------------------------------------------------------
__device__ __forceinline__ int tri_row_of(int idx) {
    float f = sqrtf(8.0f * (float)idx + 1.0f);
    int i = (int)((f - 1.0f) * 0.5f);
    while ((i + 1) * (i + 2) / 2 <= idx) ++i;
    while (i * (i + 1) / 2 > idx) --i;
    return i;
}

extern "C" __global__ void __launch_bounds__(256)
chol_kernel(const float* __restrict__ sigma) {
    extern __shared__ float sm[];   // 32896 floats
    const int b = blockIdx.x;
    const int tid = threadIdx.x;
    const float* A = sigma + (size_t)b * NN * NN;

    for (int idx = tid; idx < 32896; idx += 256) {
        int i = tri_row_of(idx);
        int j = idx - i * (i + 1) / 2;
        float v = A[i * NN + j];
        if (i == j) v += 1e-4f;
        sm[idx] = v;
    }
    __syncthreads();

    __shared__ float sdiag;
    float acc = 0.0f;
    const int base_i = tid * (tid + 1) / 2;

    for (int j = 0; j < NN; ++j) {
        if (tid == j) {
            float d = sm[j * (j + 1) / 2 + j] - acc;
            sdiag = sqrtf(fmaxf(d, 1e-20f));
            sm[j * (j + 1) / 2 + j] = sdiag;
        }
        __syncthreads();
        float dinv = 1.0f / sdiag;
        if (tid > j) {
            const int base_j = j * (j + 1) / 2;
            float s = sm[base_i + j];
            int k = 0;
            for (; k + 4 <= j; k += 4) {
                s -= sm[base_i + k]     * sm[base_j + k];
                s -= sm[base_i + k + 1] * sm[base_j + k + 1];
                s -= sm[base_i + k + 2] * sm[base_j + k + 2];
                s -= sm[base_i + k + 3] * sm[base_j + k + 3];
            }
            for (; k < j; ++k) s -= sm[base_i + k] * sm[base_j + k];
            float lij = s * dinv;
            sm[base_i + j] = lij;
            acc += lij * lij;
        }
        __syncthreads();
    }

    float* Lb  = g_L  + (size_t)b * NN * NN;
    float* LTb = g_LT + (size_t)b * NN * NN;
    for (int idx = tid; idx < NN * NN; idx += 256) {
        int i = idx >> 8, j = idx & 255;
        Lb[idx] = (j <= i) ? sm[i * (i + 1) / 2 + j] : 0.0f;
    }
    for (int idx = tid; idx < NN * NN; idx += 256) {
        int r = idx >> 8, c = idx & 255;
        LTb[idx] = (r <= c) ? sm[c * (c + 1) / 2 + r] : 0.0f;
    }
}

// ---------------------------------------------------------------------------
// Fast simplex projection for 256 values held by threads tid<256.
// Register bitonic (shfl for j<32, smem for j>=32) + shuffle cumsum +
// __syncthreads_count for rho. Returns max(wv - theta, 0) for tid<256.
// Needs: ssort[256], scs[256], swsumf[8].
// ---------------------------------------------------------------------------
__device__ __forceinline__ float simplex_proj_fast(
    float wv, float z, int tid, int lane,
    float* ssort, float* scs, float* swsumf)
{
    float x = wv;   // sorted value (valid tid<256)

#define SP_SHFL(kk, jj) \
    if (tid < 256) { \
        float o = __shfl_xor_sync(0xffffffffu, x, (jj)); \
        bool keepMax = (((tid & (kk)) == 0) == ((tid & (jj)) == 0)); \
        x = keepMax ? fmaxf(x, o) : fminf(x, o); \
    }
#define SP_SMEM(kk, jj) { \
    if (tid < 256) ssort[tid] = x; \
    __syncthreads(); \
    if (tid < 256) { \
        float o = ssort[tid ^ (jj)]; \
        bool keepMax = (((tid & (kk)) == 0) == ((tid & (jj)) == 0)); \
        x = keepMax ? fmaxf(x, o) : fminf(x, o); \
    } \
    __syncthreads(); }

    SP_SHFL(2, 1)
    SP_SHFL(4, 2)  SP_SHFL(4, 1)
    SP_SHFL(8, 4)  SP_SHFL(8, 2)  SP_SHFL(8, 1)
    SP_SHFL(16, 8) SP_SHFL(16, 4) SP_SHFL(16, 2) SP_SHFL(16, 1)
    SP_SHFL(32, 16) SP_SHFL(32, 8) SP_SHFL(32, 4) SP_SHFL(32, 2) SP_SHFL(32, 1)
    SP_SMEM(64, 32)
    SP_SHFL(64, 16) SP_SHFL(64, 8) SP_SHFL(64, 4) SP_SHFL(64, 2) SP_SHFL(64, 1)
    SP_SMEM(128, 64) SP_SMEM(128, 32)
    SP_SHFL(128, 16) SP_SHFL(128, 8) SP_SHFL(128, 4) SP_SHFL(128, 2) SP_SHFL(128, 1)
    SP_SMEM(256, 128) SP_SMEM(256, 64) SP_SMEM(256, 32)
    SP_SHFL(256, 16) SP_SHFL(256, 8) SP_SHFL(256, 4) SP_SHFL(256, 2) SP_SHFL(256, 1)
#undef SP_SHFL
#undef SP_SMEM

    // inclusive cumsum of sorted (descending) values
    float inc = 0.0f;
    if (tid < 256) {
        inc = x;
        #pragma unroll
        for (int off = 1; off < 32; off <<= 1) {
            float v = __shfl_up_sync(0xffffffffu, inc, off);
            if (lane >= off) inc += v;
        }
        if (lane == 31) swsumf[tid >> 5] = inc;   // warp totals (8)
    }
    __syncthreads();
    bool cond = false;
    if (tid < 256) {
        float pre = 0.0f;
        int w = tid >> 5;
        #pragma unroll
        for (int q = 0; q < 8; ++q) if (q < w) pre += swsumf[q];
        float cs = inc + pre;
        scs[tid] = cs;
        cond = (x - (cs - z) / (float)(tid + 1)) > 0.0f;
    }
    int rho = __syncthreads_count(cond ? 1 : 0);   // barrier: scs visible after
    float theta = (scs[rho - 1] - z) / (float)rho;
    return fmaxf(wv - theta, 0.0f);
}

// ---------------------------------------------------------------------------
// Compute u = L^T w and muw. All 1024 threads. sw holds w (256), sbuf scratch
// (>=1024 floats), swsumf 8 floats.
// ---------------------------------------------------------------------------
__device__ __forceinline__ void compute_u_muw_1024(
    int b, int tid, int lane, const float* __restrict__ mu, float lamscale,
    const float* sw, float* sbuf, float* swsumf)
{
    // muw = sum mue * w (threads < 256)
    float p = 0.0f;
    if (tid < 256) p = mu[b * NN + tid] * lamscale * sw[tid];
    if (tid < 256) {
        #pragma unroll
        for (int off = 16; off > 0; off >>= 1)
            p += __shfl_down_sync(0xffffffffu, p, off);
        if (lane == 0) swsumf[tid >> 5] = p;
    }

    // u[n] = sum_m L[m][n] * w[m], split 4 ways over m
    const int n = tid & 255, q = tid >> 8;
    const float* Lb = g_L + (size_t)b * NN * NN + (size_t)(64 * q) * NN + n;
    float acc = 0.0f;
    #pragma unroll 8
    for (int m = 0; m < 64; ++m) acc += Lb[m * NN] * sw[64 * q + m];
    sbuf[q * 256 + n] = acc;
    __syncthreads();
    if (tid < 256)
        g_u[b * NN + tid] = sbuf[tid] + sbuf[256 + tid] + sbuf[512 + tid] + sbuf[768 + tid];
    if (tid == 0) {
        float s = 0.0f;
        #pragma unroll
        for (int q2 = 0; q2 < 8; ++q2) s += swsumf[q2];
        g_muw[b] = s;
    }
}

// ---------------------------------------------------------------------------
// Init kernel: w0 = proj(1/n), then u, muw.  1024 threads per batch.
// ---------------------------------------------------------------------------
extern "C" __global__ void __launch_bounds__(1024)
init_kernel(const float* __restrict__ mu,
            const int* __restrict__ p_crisis, const int* __restrict__ p_lambda)
{
    __shared__ float ssort[256], scs[256], sw[256];
    __shared__ float sbuf[1024];
    __shared__ float swsumf[8];

    const int b = blockIdx.x;
    const int tid = threadIdx.x;
    const int lane = tid & 31;
    const float crisis = (float)(*p_crisis);
    const int lam = *p_lambda;
    const float lamscale = (lam > 0) ? (1.0f + 1.0f / fmaxf((float)lam, 0.1f)) : 1.0f;

    const float fl = (tid == BIL) ? 0.5f * crisis : 0.0f;
    const float z = 1.0f - 0.5f * crisis;
    float v = (1.0f / (float)NN) - fl;
    float pw = simplex_proj_fast(v, z, tid, lane, ssort, scs, swsumf) + fl;
    if (tid < 256) { g_w[b * NN + tid] = pw; sw[tid] = pw; }
    __syncthreads();
    compute_u_muw_1024(b, tid, lane, mu, lamscale, sw, sbuf, swsumf);
}

// ---------------------------------------------------------------------------
// Losses: one warp per scenario, fp16 eps (L2-resident), fp32 accumulate.
// losses[b,s] = -(muw + eps[b,s,:].u[b,:])
// ---------------------------------------------------------------------------
extern "C" __global__ void __launch_bounds__(256)
loss_kernel()
{
    __shared__ float4 su4[64];
    __shared__ float smuw;
    const int blk = blockIdx.x;
    const int b = blk / (NS / 8);
    const int s0 = (blk % (NS / 8)) * 8;
    const int tid = threadIdx.x;

    if (tid < 64) su4[tid] = ((const float4*)(g_u + b * NN))[tid];
    if (tid == 0) smuw = g_muw[b];
    __syncthreads();

    const int warp = tid >> 5, lane = tid & 31;
    const int s = s0 + warp;
    // lane loads 8 halves (16B): elements [lane*8, lane*8+8)
    const uint4* ep = (const uint4*)(g_eps16 + ((size_t)b * NS + s) * NN);
    uint4 raw = ep[lane];
    float4 u0 = su4[2 * lane];
    float4 u1 = su4[2 * lane + 1];
    float2 e0 = __half22float2(*(const __half2*)&raw.x);
    float2 e1 = __half22float2(*(const __half2*)&raw.y);
    float2 e2 = __half22float2(*(const __half2*)&raw.z);
    float2 e3 = __half22float2(*(const __half2*)&raw.w);
    float dot = e0.x * u0.x + e0.y * u0.y + e1.x * u0.z + e1.y * u0.w
              + e2.x * u1.x + e2.y * u1.y + e3.x * u1.z + e3.y * u1.w;
    #pragma unroll
    for (int off = 16; off > 0; off >>= 1)
        dot += __shfl_down_sync(0xffffffffu, dot, off);
    if (lane == 0) g_losses[b * NS + s] = -(smuw + dot);
}

// ---------------------------------------------------------------------------
// Iteration kernel, 1024 threads per batch.
// ---------------------------------------------------------------------------
extern "C" __global__ void __launch_bounds__(1024)
iter_kernel(const float* __restrict__ mu,
            const int* __restrict__ p_crisis, const int* __restrict__ p_lambda,
            int t, float* __restrict__ out)
{
    __shared__ unsigned skey[NS];
    __shared__ int ssel[NS];
    __shared__ int shist[256];
    __shared__ float sbuf[2048];            // gather partials (float2[8][128]) / matvec partials
    __shared__ float svv[256], sw[256], ssort[256], scs[256];
    __shared__ float swsumf[8];
    __shared__ int swsum[32];
    __shared__ unsigned s_P;
    __shared__ int s_k;

    const int b = blockIdx.x;
    const int tid = threadIdx.x;
    const int lane = tid & 31;
    const int warp = tid >> 5;

    // losses -> monotone sortable keys
    for (int s = tid; s < NS; s += 1024) {
        unsigned ub = __float_as_uint(g_losses[b * NS + s]);
        skey[s] = (ub & 0x80000000u) ? ~ub : (ub | 0x80000000u);
    }
    if (tid == 0) { s_P = 0u; s_k = KK; }

    // 4-pass MSD radix select for the K-th largest key
    #pragma unroll
    for (int p = 0; p < 4; ++p) {
        const int shift = 24 - 8 * p;
        if (tid < 256) shist[tid] = 0;
        __syncthreads();
        const unsigned Pc = s_P;
        const int kcur = s_k;
        for (int s = tid; s < NS; s += 1024) {
            unsigned key = skey[s];
            bool match = (p == 0) || ((key >> (shift + 8)) == (Pc >> (shift + 8)));
            if (match) atomicAdd(&shist[(key >> shift) & 255u], 1);
        }
        __syncthreads();
        if (warp == 0) {
            // lane handles 8 digits in descending order
            int c[8]; int sum = 0;
            #pragma unroll
            for (int j = 0; j < 8; ++j) { c[j] = shist[255 - (lane * 8 + j)]; sum += c[j]; }
            int incs = sum;
            #pragma unroll
            for (int off = 1; off < 32; off <<= 1) {
                int v = __shfl_up_sync(0xffffffffu, incs, off);
                if (lane >= off) incs += v;
            }
            int run = incs - sum;   // exclusive
            #pragma unroll
            for (int j = 0; j < 8; ++j) {
                int C1 = run; run += c[j];
                if (run >= kcur && C1 < kcur) {
                    s_P = Pc | ((unsigned)(255 - (lane * 8 + j)) << shift);
                    s_k = kcur - C1;
                }
            }
        }
        __syncthreads();
    }
    const unsigned T = s_P;

    // deterministic compaction of selected scenarios (key >= T)
    bool m0 = skey[tid] >= T;                                   // s = tid (tid < 1024 < NS)
    bool m1 = (tid + 1024 < NS) && (skey[tid + 1024] >= T);     // s = tid + 1024
    int cnt = (int)m0 + (int)m1;
    {
        int incs = cnt;
        #pragma unroll
        for (int off = 1; off < 32; off <<= 1) {
            int v = __shfl_up_sync(0xffffffffu, incs, off);
            if (lane >= off) incs += v;
        }
        if (lane == 31) swsum[warp] = incs;
        __syncthreads();
        if (warp == 0) {
            int v = swsum[lane];
            #pragma unroll
            for (int off = 1; off < 32; off <<= 1) {
                int x = __shfl_up_sync(0xffffffffu, v, off);
                if (lane >= off) v += x;
            }
            swsum[lane] = v;   // inclusive warp totals
        }
        __syncthreads();
        int ofs = (incs - cnt) + (warp > 0 ? swsum[warp - 1] : 0);
        if (m0) ssel[ofs++] = tid;
        if (m1) ssel[ofs] = tid + 1024;
    }
    __syncthreads();
    const int total = swsum[31];
    const float coef = 1.0f / fmaxf((float)total, (float)KK);
    const float summ = (float)total * coef;

    // v[n] = coef * sum_{selected s} eps16[b,s,n]  (8-way split over rows)
    {
        const int grp = tid >> 7, cp = tid & 127;
        const __half2* e2 = (const __half2*)g_eps16 + (size_t)b * NS * 128;
        float2 acc = make_float2(0.0f, 0.0f);
        for (int i = grp; i < total; i += 8) {
            float2 f = __half22float2(e2[(size_t)ssel[i] * 128 + cp]);
            acc.x += f.x; acc.y += f.y;
        }
        ((float2*)sbuf)[grp * 128 + cp] = acc;
    }
    __syncthreads();
    if (tid < 128) {
        float2 s = make_float2(0.0f, 0.0f);
        #pragma unroll
        for (int q = 0; q < 8; ++q) {
            float2 v = ((const float2*)sbuf)[q * 128 + tid];
            s.x += v.x; s.y += v.y;
        }
        svv[2 * tid] = s.x * coef;
        svv[2 * tid + 1] = s.y * coef;
    }
    __syncthreads();

    // g[n] = -(summ*mue[n] + sum_m L[n][m] v[m])  via LT, split 4 ways over m
    const int lam = *p_lambda;
    const float lamscale = (lam > 0) ? (1.0f + 1.0f / fmaxf((float)lam, 0.1f)) : 1.0f;
    {
        const int n = tid & 255, q = tid >> 8;
        const float* LTb = g_LT + (size_t)b * NN * NN + (size_t)(64 * q) * NN + n;
        float acc = 0.0f;
        #pragma unroll 8
        for (int m = 0; m < 64; ++m) acc += LTb[m * NN] * svv[64 * q + m];
        sbuf[q * 256 + n] = acc;
    }
    __syncthreads();

    // projected update (threads < 256 own components)
    const float crisis = (float)(*p_crisis);
    const float z = 1.0f - 0.5f * crisis;
    const float lr = 0.5f / sqrtf((float)t + 1.0f);
    float wv = 0.0f, fl = 0.0f;
    if (tid < 256) {
        fl = (tid == BIL) ? 0.5f * crisis : 0.0f;
        const float mue = mu[b * NN + tid] * lamscale;
        const float lv = sbuf[tid] + sbuf[256 + tid] + sbuf[512 + tid] + sbuf[768 + tid];
        const float gval = -(summ * mue + lv);
        wv = g_w[b * NN + tid] - lr * gval - fl;
    }
    __syncthreads();
    float pw = simplex_proj_fast(wv, z, tid, lane, ssort, scs, swsumf) + fl;
    if (tid < 256) { g_w[b * NN + tid] = pw; sw[tid] = pw; }
    __syncthreads();

    if (t == NITERS - 1) {
        // final clamp + renormalize
        float wc = (tid < 256) ? fmaxf(pw, 0.0f) : 0.0f;
        float r = wc;
        if (tid < 256) {
            #pragma unroll
            for (int off = 16; off > 0; off >>= 1)
                r += __shfl_down_sync(0xffffffffu, r, off);
            if (lane == 0) swsumf[warp] = r;
        }
        __syncthreads();
        if (tid < 256) {
            float s = 0.0f;
            #pragma unroll
            for (int q = 0; q < 8; ++q) s += swsumf[q];
            out[b * NN + tid] = wc / (s + 1e-8f);
        }
    } else {
        compute_u_muw_1024(b, tid, lane, mu, lamscale, sw, sbuf, swsumf);
    }
}

// ---------------------------------------------------------------------------
extern "C" void kernel_launch(void* const* d_in, const int* in_sizes, int n_in,
                              void* d_out, int out_size)
{
    const float* mu     = (const float*)d_in[0];
    const float* sigma  = (const float*)d_in[1];
    const float* eps    = (const float*)d_in[2];
    const int*   crisis = (const int*)d_in[3];
    const int*   lambda = (const int*)d_in[4];
    float* out = (float*)d_out;

    cudaFuncSetAttribute(chol_kernel, cudaFuncAttributeMaxDynamicSharedMemorySize,
                         32896 * sizeof(float));

    conv_kernel<<<32000, 256>>>(eps);
    chol_kernel<<<NB, 256, 32896 * sizeof(float)>>>(sigma);
    init_kernel<<<NB, 1024>>>(mu, crisis, lambda);
    for (int t = 0; t < NITERS; ++t) {
        loss_kernel<<<NB * (NS / 8), 256>>>();
        iter_kernel<<<NB, 1024>>>(mu, crisis, lambda, t, out);
    }
}

// round 3
// speedup vs baseline: 2.0448x; 1.5425x over previous
#include <cuda_runtime.h>
#include <cuda_fp16.h>
#include <math.h>

// Problem constants
#define NB 64
#define NN 256
#define NS 2000
#define KK 100
#define BIL 4
#define NITERS 200

// Device scratch (fp16 matrices -> whole per-iter working set fits in L2)
__device__ __align__(16) __half g_L16[(size_t)NB * NN * NN];   // 8.4MB  L[b][m][n]
__device__ __align__(16) __half g_LT16[(size_t)NB * NN * NN];  // 8.4MB  LT[b][m][n]=L[n][m]
__device__ float g_w[NB * NN];
__device__ float g_u[NB * NN];
__device__ float g_muw[NB];
__device__ float g_losses[NB * NS];
// eps16 PERMUTED layout: uint4 slot l of a row holds logical elements
// {4l..4l+4, 128+4l..128+4l+4} as 8 halves.
__device__ __align__(16) __half g_eps16[(size_t)NB * NS * NN];  // 65.5MB

// ---------------------------------------------------------------------------
// eps fp32 -> fp16 permuted conversion (one thread per output uint4)
// ---------------------------------------------------------------------------
extern "C" __global__ void __launch_bounds__(256)
conv_kernel(const float* __restrict__ eps)
{
    size_t gid = (size_t)blockIdx.x * blockDim.x + threadIdx.x;
    const size_t total = (size_t)NB * NS * 32;
    if (gid >= total) return;
    size_t row = gid >> 5;
    int l = (int)(gid & 31);
    const float4* e4 = (const float4*)eps + row * 64;
    float4 f0 = __ldcs(e4 + l);        // elements 4l..4l+4
    float4 f1 = __ldcs(e4 + 32 + l);   // elements 128+4l..
    uint4 o;
    *(__half2*)&o.x = __floats2half2_rn(f0.x, f0.y);
    *(__half2*)&o.y = __floats2half2_rn(f0.z, f0.w);
    *(__half2*)&o.z = __floats2half2_rn(f1.x, f1.y);
    *(__half2*)&o.w = __floats2half2_rn(f1.z, f1.w);
    ((uint4*)g_eps16)[row * 32 + l] = o;
}

// ---------------------------------------------------------------------------
// Cholesky: one block per batch, packed lower triangle in smem; writes fp16
// L and LT directly.
// ---------------------------------------------------------------------------
__device__ __forceinline__ int tri_row_of(int idx) {
    float f = sqrtf(8.0f * (float)idx + 1.0f);
    int i = (int)((f - 1.0f) * 0.5f);
    while ((i + 1) * (i + 2) / 2 <= idx) ++i;
    while (i * (i + 1) / 2 > idx) --i;
    return i;
}

extern "C" __global__ void __launch_bounds__(256)
chol_kernel(const float* __restrict__ sigma) {
    extern __shared__ float sm[];   // 32896 floats
    const int b = blockIdx.x;
    const int tid = threadIdx.x;
    const float* A = sigma + (size_t)b * NN * NN;

    for (int idx = tid; idx < 32896; idx += 256) {
        int i = tri_row_of(idx);
        int j = idx - i * (i + 1) / 2;
        float v = A[i * NN + j];
        if (i == j) v += 1e-4f;
        sm[idx] = v;
    }
    __syncthreads();

    __shared__ float sdiag;
    float acc = 0.0f;
    const int base_i = tid * (tid + 1) / 2;

    for (int j = 0; j < NN; ++j) {
        if (tid == j) {
            float d = sm[j * (j + 1) / 2 + j] - acc;
            sdiag = sqrtf(fmaxf(d, 1e-20f));
            sm[j * (j + 1) / 2 + j] = sdiag;
        }
        __syncthreads();
        float dinv = 1.0f / sdiag;
        if (tid > j) {
            const int base_j = j * (j + 1) / 2;
            float s = sm[base_i + j];
            int k = 0;
            for (; k + 4 <= j; k += 4) {
                s -= sm[base_i + k]     * sm[base_j + k];
                s -= sm[base_i + k + 1] * sm[base_j + k + 1];
                s -= sm[base_i + k + 2] * sm[base_j + k + 2];
                s -= sm[base_i + k + 3] * sm[base_j + k + 3];
            }
            for (; k < j; ++k) s -= sm[base_i + k] * sm[base_j + k];
            float lij = s * dinv;
            sm[base_i + j] = lij;
            acc += lij * lij;
        }
        __syncthreads();
    }

    __half* Lb  = g_L16  + (size_t)b * NN * NN;
    __half* LTb = g_LT16 + (size_t)b * NN * NN;
    for (int idx = tid; idx < NN * NN; idx += 256) {
        int i = idx >> 8, j = idx & 255;
        Lb[idx] = __float2half_rn((j <= i) ? sm[i * (i + 1) / 2 + j] : 0.0f);
    }
    for (int idx = tid; idx < NN * NN; idx += 256) {
        int r = idx >> 8, c = idx & 255;
        LTb[idx] = __float2half_rn((r <= c) ? sm[c * (c + 1) / 2 + r] : 0.0f);
    }
}

// ---------------------------------------------------------------------------
// Fast simplex projection (values on tid<256): register bitonic + shuffle
// cumsum + __syncthreads_count.
// ---------------------------------------------------------------------------
__device__ __forceinline__ float simplex_proj_fast(
    float wv, float z, int tid, int lane,
    float* ssort, float* scs, float* swsumf)
{
    float x = wv;

#define SP_SHFL(kk, jj) \
    if (tid < 256) { \
        float o = __shfl_xor_sync(0xffffffffu, x, (jj)); \
        bool keepMax = (((tid & (kk)) == 0) == ((tid & (jj)) == 0)); \
        x = keepMax ? fmaxf(x, o) : fminf(x, o); \
    }
#define SP_SMEM(kk, jj) { \
    if (tid < 256) ssort[tid] = x; \
    __syncthreads(); \
    if (tid < 256) { \
        float o = ssort[tid ^ (jj)]; \
        bool keepMax = (((tid & (kk)) == 0) == ((tid & (jj)) == 0)); \
        x = keepMax ? fmaxf(x, o) : fminf(x, o); \
    } \
    __syncthreads(); }

    SP_SHFL(2, 1)
    SP_SHFL(4, 2)  SP_SHFL(4, 1)
    SP_SHFL(8, 4)  SP_SHFL(8, 2)  SP_SHFL(8, 1)
    SP_SHFL(16, 8) SP_SHFL(16, 4) SP_SHFL(16, 2) SP_SHFL(16, 1)
    SP_SHFL(32, 16) SP_SHFL(32, 8) SP_SHFL(32, 4) SP_SHFL(32, 2) SP_SHFL(32, 1)
    SP_SMEM(64, 32)
    SP_SHFL(64, 16) SP_SHFL(64, 8) SP_SHFL(64, 4) SP_SHFL(64, 2) SP_SHFL(64, 1)
    SP_SMEM(128, 64) SP_SMEM(128, 32)
    SP_SHFL(128, 16) SP_SHFL(128, 8) SP_SHFL(128, 4) SP_SHFL(128, 2) SP_SHFL(128, 1)
    SP_SMEM(256, 128) SP_SMEM(256, 64) SP_SMEM(256, 32)
    SP_SHFL(256, 16) SP_SHFL(256, 8) SP_SHFL(256, 4) SP_SHFL(256, 2) SP_SHFL(256, 1)
#undef SP_SHFL
#undef SP_SMEM

    float inc = 0.0f;
    if (tid < 256) {
        inc = x;
        #pragma unroll
        for (int off = 1; off < 32; off <<= 1) {
            float v = __shfl_up_sync(0xffffffffu, inc, off);
            if (lane >= off) inc += v;
        }
        if (lane == 31) swsumf[tid >> 5] = inc;
    }
    __syncthreads();
    bool cond = false;
    if (tid < 256) {
        float pre = 0.0f;
        int w = tid >> 5;
        #pragma unroll
        for (int q = 0; q < 8; ++q) if (q < w) pre += swsumf[q];
        float cs = inc + pre;
        scs[tid] = cs;
        cond = (x - (cs - z) / (float)(tid + 1)) > 0.0f;
    }
    int rho = __syncthreads_count(cond ? 1 : 0);
    float theta = (scs[rho - 1] - z) / (float)rho;
    return fmaxf(wv - theta, 0.0f);
}

// ---------------------------------------------------------------------------
// Compute u = L^T w and muw. 1024 threads; 8-way split over m, half2 columns.
// sw: w[256]; sbuf: >=2048 floats; swsumf: 8 floats.
// ---------------------------------------------------------------------------
__device__ __forceinline__ void compute_u_muw_1024(
    int b, int tid, int lane, const float* __restrict__ mu, float lamscale,
    const float* sw, float* sbuf, float* swsumf)
{
    float p = 0.0f;
    if (tid < 256) {
        p = mu[b * NN + tid] * lamscale * sw[tid];
        #pragma unroll
        for (int off = 16; off > 0; off >>= 1)
            p += __shfl_down_sync(0xffffffffu, p, off);
        if (lane == 0) swsumf[tid >> 5] = p;
    }

    // u[n] = sum_m L[m][n] w[m]; thread (q,cp) handles n=2cp,2cp+1, m in [32q,32q+32)
    const int q = tid >> 7, cp = tid & 127;
    const __half2* L2 = (const __half2*)(g_L16 + (size_t)b * NN * NN) + (size_t)(32 * q) * 128 + cp;
    float2 acc = make_float2(0.0f, 0.0f);
    #pragma unroll 8
    for (int m = 0; m < 32; ++m) {
        float2 f = __half22float2(__ldg(L2 + m * 128));
        float wm = sw[32 * q + m];
        acc.x += f.x * wm; acc.y += f.y * wm;
    }
    ((float2*)sbuf)[q * 128 + cp] = acc;
    __syncthreads();
    if (tid < 128) {
        float2 s = make_float2(0.0f, 0.0f);
        #pragma unroll
        for (int r = 0; r < 8; ++r) {
            float2 v = ((const float2*)sbuf)[r * 128 + tid];
            s.x += v.x; s.y += v.y;
        }
        ((float2*)(g_u + b * NN))[tid] = s;
    }
    if (tid == 0) {
        float s = 0.0f;
        #pragma unroll
        for (int r = 0; r < 8; ++r) s += swsumf[r];
        g_muw[b] = s;
    }
}

// ---------------------------------------------------------------------------
// Init kernel: w0 = proj(1/n), then u, muw.
// ---------------------------------------------------------------------------
extern "C" __global__ void __launch_bounds__(1024)
init_kernel(const float* __restrict__ mu,
            const int* __restrict__ p_crisis, const int* __restrict__ p_lambda)
{
    __shared__ float ssort[256], scs[256], sw[256];
    __shared__ float sbuf[2048];
    __shared__ float swsumf[8];

    const int b = blockIdx.x;
    const int tid = threadIdx.x;
    const int lane = tid & 31;
    const float crisis = (float)(*p_crisis);
    const int lam = *p_lambda;
    const float lamscale = (lam > 0) ? (1.0f + 1.0f / fmaxf((float)lam, 0.1f)) : 1.0f;

    const float fl = (tid == BIL) ? 0.5f * crisis : 0.0f;
    const float z = 1.0f - 0.5f * crisis;
    float v = (1.0f / (float)NN) - fl;
    float pw = simplex_proj_fast(v, z, tid, lane, ssort, scs, swsumf) + fl;
    if (tid < 256) { g_w[b * NN + tid] = pw; sw[tid] = pw; }
    __syncthreads();
    compute_u_muw_1024(b, tid, lane, mu, lamscale, sw, sbuf, swsumf);
}

// ---------------------------------------------------------------------------
// Losses: 2 scenarios per warp, permuted fp16 eps, conflict-free u LDS.
// ---------------------------------------------------------------------------
__device__ __forceinline__ float dot8(uint4 raw, float4 u0, float4 u1) {
    float2 e0 = __half22float2(*(const __half2*)&raw.x);
    float2 e1 = __half22float2(*(const __half2*)&raw.y);
    float2 e2 = __half22float2(*(const __half2*)&raw.z);
    float2 e3 = __half22float2(*(const __half2*)&raw.w);
    return e0.x * u0.x + e0.y * u0.y + e1.x * u0.z + e1.y * u0.w
         + e2.x * u1.x + e2.y * u1.y + e3.x * u1.z + e3.y * u1.w;
}

extern "C" __global__ void __launch_bounds__(256)
loss_kernel()
{
    __shared__ float4 su4[64];     // su4[j] = u[4j..4j+4)
    __shared__ float smuw;
    const int blk = blockIdx.x;
    const int b = blk / (NS / 16);
    const int sbase = (blk % (NS / 16)) * 16;
    const int tid = threadIdx.x;

    if (tid < 64) su4[tid] = ((const float4*)(g_u + b * NN))[tid];
    if (tid == 0) smuw = g_muw[b];
    __syncthreads();

    const int warp = tid >> 5, lane = tid & 31;
    const int s0 = sbase + warp * 2;
    const uint4* ep = (const uint4*)g_eps16 + ((size_t)b * NS + s0) * 32;
    uint4 ra = __ldg(ep + lane);
    uint4 rb = __ldg(ep + 32 + lane);
    float4 u0 = su4[lane];
    float4 u1 = su4[32 + lane];
    float d0 = dot8(ra, u0, u1);
    float d1 = dot8(rb, u0, u1);
    #pragma unroll
    for (int off = 16; off > 0; off >>= 1) {
        d0 += __shfl_down_sync(0xffffffffu, d0, off);
        d1 += __shfl_down_sync(0xffffffffu, d1, off);
    }
    if (lane == 0) {
        g_losses[b * NS + s0]     = -(smuw + d0);
        g_losses[b * NS + s0 + 1] = -(smuw + d1);
    }
}

// ---------------------------------------------------------------------------
// Iteration kernel, 1024 threads per batch.
// ---------------------------------------------------------------------------
extern "C" __global__ void __launch_bounds__(1024)
iter_kernel(const float* __restrict__ mu,
            const int* __restrict__ p_crisis, const int* __restrict__ p_lambda,
            int t, float* __restrict__ out)
{
    __shared__ unsigned skey[NS];
    __shared__ int ssel[NS];
    __shared__ int shist[256];
    __shared__ float sbuf[2048];
    __shared__ float svv[256], sw[256], ssort[256], scs[256];
    __shared__ float swsumf[8];
    __shared__ int swsum[32];
    __shared__ unsigned s_P;
    __shared__ int s_k;

    const int b = blockIdx.x;
    const int tid = threadIdx.x;
    const int lane = tid & 31;
    const int warp = tid >> 5;

    for (int s = tid; s < NS; s += 1024) {
        unsigned ub = __float_as_uint(g_losses[b * NS + s]);
        skey[s] = (ub & 0x80000000u) ? ~ub : (ub | 0x80000000u);
    }
    if (tid == 0) { s_P = 0u; s_k = KK; }

    // 4-pass MSD radix select for the K-th largest key
    #pragma unroll
    for (int p = 0; p < 4; ++p) {
        const int shift = 24 - 8 * p;
        if (tid < 256) shist[tid] = 0;
        __syncthreads();
        const unsigned Pc = s_P;
        const int kcur = s_k;
        for (int s = tid; s < NS; s += 1024) {
            unsigned key = skey[s];
            bool match = (p == 0) || ((key >> (shift + 8)) == (Pc >> (shift + 8)));
            if (match) atomicAdd(&shist[(key >> shift) & 255u], 1);
        }
        __syncthreads();
        if (warp == 0) {
            int c[8]; int sum = 0;
            #pragma unroll
            for (int j = 0; j < 8; ++j) { c[j] = shist[255 - (lane * 8 + j)]; sum += c[j]; }
            int incs = sum;
            #pragma unroll
            for (int off = 1; off < 32; off <<= 1) {
                int v = __shfl_up_sync(0xffffffffu, incs, off);
                if (lane >= off) incs += v;
            }
            int run = incs - sum;
            #pragma unroll
            for (int j = 0; j < 8; ++j) {
                int C1 = run; run += c[j];
                if (run >= kcur && C1 < kcur) {
                    s_P = Pc | ((unsigned)(255 - (lane * 8 + j)) << shift);
                    s_k = kcur - C1;
                }
            }
        }
        __syncthreads();
    }
    const unsigned T = s_P;

    // deterministic compaction of selected scenarios
    bool m0 = skey[tid] >= T;
    bool m1 = (tid + 1024 < NS) && (skey[tid + 1024] >= T);
    int cnt = (int)m0 + (int)m1;
    {
        int incs = cnt;
        #pragma unroll
        for (int off = 1; off < 32; off <<= 1) {
            int v = __shfl_up_sync(0xffffffffu, incs, off);
            if (lane >= off) incs += v;
        }
        if (lane == 31) swsum[warp] = incs;
        __syncthreads();
        if (warp == 0) {
            int v = swsum[lane];
            #pragma unroll
            for (int off = 1; off < 32; off <<= 1) {
                int x = __shfl_up_sync(0xffffffffu, v, off);
                if (lane >= off) v += x;
            }
            swsum[lane] = v;
        }
        __syncthreads();
        int ofs = (incs - cnt) + (warp > 0 ? swsum[warp - 1] : 0);
        if (m0) ssel[ofs++] = tid;
        if (m1) ssel[ofs] = tid + 1024;
    }
    __syncthreads();
    const int total = swsum[31];
    const float coef = 1.0f / fmaxf((float)total, (float)KK);
    const float summ = (float)total * coef;

    // v accumulate over selected rows (permuted layout), 8-way row split
    {
        const int grp = tid >> 7, cp = tid & 127;
        const __half2* e2 = (const __half2*)g_eps16 + (size_t)b * NS * 128;
        float2 acc = make_float2(0.0f, 0.0f);
        for (int i = grp; i < total; i += 8) {
            float2 f = __half22float2(__ldg(e2 + (size_t)ssel[i] * 128 + cp));
            acc.x += f.x; acc.y += f.y;
        }
        ((float2*)sbuf)[grp * 128 + cp] = acc;
    }
    __syncthreads();
    if (tid < 128) {
        float2 s = make_float2(0.0f, 0.0f);
        #pragma unroll
        for (int r = 0; r < 8; ++r) {
            float2 v = ((const float2*)sbuf)[r * 128 + tid];
            s.x += v.x; s.y += v.y;
        }
        // un-permute: memory half2 cp -> logical index n0
        int l = tid >> 2, rr = 2 * (tid & 3);
        int n0 = (rr < 4) ? (4 * l + rr) : (128 + 4 * l + (rr - 4));
        svv[n0] = s.x * coef;
        svv[n0 + 1] = s.y * coef;
    }
    __syncthreads();

    // lv[n] = sum_m L[n][m] v[m] via LT16; thread (q,cp): n=2cp,2cp+1, m in [32q,32q+32)
    const int lam = *p_lambda;
    const float lamscale = (lam > 0) ? (1.0f + 1.0f / fmaxf((float)lam, 0.1f)) : 1.0f;
    {
        const int q = tid >> 7, cp = tid & 127;
        const __half2* LT2 = (const __half2*)(g_LT16 + (size_t)b * NN * NN) + (size_t)(32 * q) * 128 + cp;
        float2 acc = make_float2(0.0f, 0.0f);
        #pragma unroll 8
        for (int m = 0; m < 32; ++m) {
            float2 f = __half22float2(__ldg(LT2 + m * 128));
            float vm = svv[32 * q + m];
            acc.x += f.x * vm; acc.y += f.y * vm;
        }
        __syncthreads();   // svv reads done before sbuf overwritten
        ((float2*)sbuf)[q * 128 + cp] = acc;
    }
    __syncthreads();

    // projected update (threads < 256 own components)
    const float crisis = (float)(*p_crisis);
    const float z = 1.0f - 0.5f * crisis;
    const float lr = 0.5f / sqrtf((float)t + 1.0f);
    float wv = 0.0f, fl = 0.0f;
    if (tid < 256) {
        fl = (tid == BIL) ? 0.5f * crisis : 0.0f;
        const float mue = mu[b * NN + tid] * lamscale;
        const int cp = tid >> 1, sel = tid & 1;
        float lv = 0.0f;
        #pragma unroll
        for (int r = 0; r < 8; ++r) {
            float2 v = ((const float2*)sbuf)[r * 128 + cp];
            lv += sel ? v.y : v.x;
        }
        const float gval = -(summ * mue + lv);
        wv = g_w[b * NN + tid] - lr * gval - fl;
    }
    __syncthreads();
    float pw = simplex_proj_fast(wv, z, tid, lane, ssort, scs, swsumf) + fl;
    if (tid < 256) { g_w[b * NN + tid] = pw; sw[tid] = pw; }
    __syncthreads();

    if (t == NITERS - 1) {
        float wc = (tid < 256) ? fmaxf(pw, 0.0f) : 0.0f;
        float r = wc;
        if (tid < 256) {
            #pragma unroll
            for (int off = 16; off > 0; off >>= 1)
                r += __shfl_down_sync(0xffffffffu, r, off);
            if (lane == 0) swsumf[tid >> 5] = r;
        }
        __syncthreads();
        if (tid < 256) {
            float s = 0.0f;
            #pragma unroll
            for (int q = 0; q < 8; ++q) s += swsumf[q];
            out[b * NN + tid] = wc / (s + 1e-8f);
        }
    } else {
        compute_u_muw_1024(b, tid, lane, mu, lamscale, sw, sbuf, swsumf);
    }
}

// ---------------------------------------------------------------------------
extern "C" void kernel_launch(void* const* d_in, const int* in_sizes, int n_in,
                              void* d_out, int out_size)
{
    const float* mu     = (const float*)d_in[0];
    const float* sigma  = (const float*)d_in[1];
    const float* eps    = (const float*)d_in[2];
    const int*   crisis = (const int*)d_in[3];
    const int*   lambda = (const int*)d_in[4];
    float* out = (float*)d_out;

    cudaFuncSetAttribute(chol_kernel, cudaFuncAttributeMaxDynamicSharedMemorySize,
                         32896 * sizeof(float));

    conv_kernel<<<16000, 256>>>(eps);
    chol_kernel<<<NB, 256, 32896 * sizeof(float)>>>(sigma);
    init_kernel<<<NB, 1024>>>(mu, crisis, lambda);
    for (int t = 0; t < NITERS; ++t) {
        loss_kernel<<<NB * (NS / 16), 256>>>();
        iter_kernel<<<NB, 1024>>>(mu, crisis, lambda, t, out);
    }
}

// round 4
// speedup vs baseline: 2.0982x; 1.0261x over previous
#include <cuda_runtime.h>
#include <cuda_fp16.h>
#include <math.h>

// Problem constants
#define NB 64
#define NN 256
#define NS 2000
#define KK 100
#define BIL 4
#define NITERS 200

// Device scratch
__device__ __align__(16) __half g_L16[(size_t)NB * NN * NN];   // 8.4MB  L[b][m][n]
__device__ __align__(16) __half g_LT16[(size_t)NB * NN * NN];  // 8.4MB  LT[b][m][n]=L[n][m]
__device__ float g_w[NB * NN];
__device__ float g_u[NB * NN];
__device__ __align__(16) float g_part[4 * NB * NS];            // 2MB partial dots
__device__ __align__(16) __half g_eps16[(size_t)NB * NS * NN]; // 65.5MB row-major [b][s][n]
__device__ __align__(16) __half g_epsT[(size_t)NB * NN * NS];  // 65.5MB transposed [b][n][s]

// ---------------------------------------------------------------------------
// eps fp32 -> fp16 row-major (one thread per 8 elements)
// ---------------------------------------------------------------------------
extern "C" __global__ void __launch_bounds__(256)
conv_kernel(const float* __restrict__ eps)
{
    size_t gid = (size_t)blockIdx.x * blockDim.x + threadIdx.x;
    const size_t total8 = (size_t)NB * NS * NN / 8;
    if (gid >= total8) return;
    const float4* e4 = (const float4*)eps;
    float4 f0 = __ldcs(e4 + 2 * gid);
    float4 f1 = __ldcs(e4 + 2 * gid + 1);
    uint4 o;
    *(__half2*)&o.x = __floats2half2_rn(f0.x, f0.y);
    *(__half2*)&o.y = __floats2half2_rn(f0.z, f0.w);
    *(__half2*)&o.z = __floats2half2_rn(f1.x, f1.y);
    *(__half2*)&o.w = __floats2half2_rn(f1.z, f1.w);
    ((uint4*)g_eps16)[gid] = o;
}

// ---------------------------------------------------------------------------
// eps fp32 -> fp16 transposed [b][n][s], tiled 64(s) x 32(n)
// ---------------------------------------------------------------------------
extern "C" __global__ void __launch_bounds__(256)
transpose_kernel(const float* __restrict__ eps)
{
    __shared__ float tile[64][33];
    const int blk = blockIdx.x;
    const int b = blk >> 8;            // 256 tiles per batch (32 s x 8 n)
    const int rest = blk & 255;
    const int st = rest >> 3;
    const int nt = rest & 7;
    const int s0 = st * 64, n0 = nt * 32;
    const int tid = threadIdx.x;

    #pragma unroll
    for (int k = 0; k < 8; ++k) {
        int idx = tid + 256 * k;
        int s = idx >> 5, n = idx & 31;
        float v = 0.0f;
        if (s0 + s < NS) v = __ldcs(&eps[((size_t)b * NS + s0 + s) * NN + n0 + n]);
        tile[s][n] = v;
    }
    __syncthreads();
    #pragma unroll
    for (int k = 0; k < 4; ++k) {
        int idx = tid + 256 * k;       // 0..1023
        int n = idx >> 5, sp = idx & 31;
        int s = 2 * sp;
        if (s0 + s < NS) {
            __half2 h = __floats2half2_rn(tile[s][n], tile[s + 1][n]);
            *(__half2*)(g_epsT + ((size_t)b * NN + n0 + n) * NS + s0 + s) = h;
        }
    }
}

// ---------------------------------------------------------------------------
// Cholesky: one block per batch, packed lower triangle in smem; fp16 L, LT.
// ---------------------------------------------------------------------------
__device__ __forceinline__ int tri_row_of(int idx) {
    float f = sqrtf(8.0f * (float)idx + 1.0f);
    int i = (int)((f - 1.0f) * 0.5f);
    while ((i + 1) * (i + 2) / 2 <= idx) ++i;
    while (i * (i + 1) / 2 > idx) --i;
    return i;
}

extern "C" __global__ void __launch_bounds__(256)
chol_kernel(const float* __restrict__ sigma) {
    extern __shared__ float sm[];   // 32896 floats
    const int b = blockIdx.x;
    const int tid = threadIdx.x;
    const float* A = sigma + (size_t)b * NN * NN;

    for (int idx = tid; idx < 32896; idx += 256) {
        int i = tri_row_of(idx);
        int j = idx - i * (i + 1) / 2;
        float v = A[i * NN + j];
        if (i == j) v += 1e-4f;
        sm[idx] = v;
    }
    __syncthreads();

    __shared__ float sdiag;
    float acc = 0.0f;
    const int base_i = tid * (tid + 1) / 2;

    for (int j = 0; j < NN; ++j) {
        if (tid == j) {
            float d = sm[j * (j + 1) / 2 + j] - acc;
            sdiag = sqrtf(fmaxf(d, 1e-20f));
            sm[j * (j + 1) / 2 + j] = sdiag;
        }
        __syncthreads();
        float dinv = 1.0f / sdiag;
        if (tid > j) {
            const int base_j = j * (j + 1) / 2;
            float s = sm[base_i + j];
            int k = 0;
            for (; k + 4 <= j; k += 4) {
                s -= sm[base_i + k]     * sm[base_j + k];
                s -= sm[base_i + k + 1] * sm[base_j + k + 1];
                s -= sm[base_i + k + 2] * sm[base_j + k + 2];
                s -= sm[base_i + k + 3] * sm[base_j + k + 3];
            }
            for (; k < j; ++k) s -= sm[base_i + k] * sm[base_j + k];
            float lij = s * dinv;
            sm[base_i + j] = lij;
            acc += lij * lij;
        }
        __syncthreads();
    }

    __half* Lb  = g_L16  + (size_t)b * NN * NN;
    __half* LTb = g_LT16 + (size_t)b * NN * NN;
    for (int idx = tid; idx < NN * NN; idx += 256) {
        int i = idx >> 8, j = idx & 255;
        Lb[idx] = __float2half_rn((j <= i) ? sm[i * (i + 1) / 2 + j] : 0.0f);
    }
    for (int idx = tid; idx < NN * NN; idx += 256) {
        int r = idx >> 8, c = idx & 255;
        LTb[idx] = __float2half_rn((r <= c) ? sm[c * (c + 1) / 2 + r] : 0.0f);
    }
}

// ---------------------------------------------------------------------------
// Fast simplex projection (values on tid<256).
// ---------------------------------------------------------------------------
__device__ __forceinline__ float simplex_proj_fast(
    float wv, float z, int tid, int lane,
    float* ssort, float* scs, float* swsumf)
{
    float x = wv;

#define SP_SHFL(kk, jj) \
    if (tid < 256) { \
        float o = __shfl_xor_sync(0xffffffffu, x, (jj)); \
        bool keepMax = (((tid & (kk)) == 0) == ((tid & (jj)) == 0)); \
        x = keepMax ? fmaxf(x, o) : fminf(x, o); \
    }
#define SP_SMEM(kk, jj) { \
    if (tid < 256) ssort[tid] = x; \
    __syncthreads(); \
    if (tid < 256) { \
        float o = ssort[tid ^ (jj)]; \
        bool keepMax = (((tid & (kk)) == 0) == ((tid & (jj)) == 0)); \
        x = keepMax ? fmaxf(x, o) : fminf(x, o); \
    } \
    __syncthreads(); }

    SP_SHFL(2, 1)
    SP_SHFL(4, 2)  SP_SHFL(4, 1)
    SP_SHFL(8, 4)  SP_SHFL(8, 2)  SP_SHFL(8, 1)
    SP_SHFL(16, 8) SP_SHFL(16, 4) SP_SHFL(16, 2) SP_SHFL(16, 1)
    SP_SHFL(32, 16) SP_SHFL(32, 8) SP_SHFL(32, 4) SP_SHFL(32, 2) SP_SHFL(32, 1)
    SP_SMEM(64, 32)
    SP_SHFL(64, 16) SP_SHFL(64, 8) SP_SHFL(64, 4) SP_SHFL(64, 2) SP_SHFL(64, 1)
    SP_SMEM(128, 64) SP_SMEM(128, 32)
    SP_SHFL(128, 16) SP_SHFL(128, 8) SP_SHFL(128, 4) SP_SHFL(128, 2) SP_SHFL(128, 1)
    SP_SMEM(256, 128) SP_SMEM(256, 64) SP_SMEM(256, 32)
    SP_SHFL(256, 16) SP_SHFL(256, 8) SP_SHFL(256, 4) SP_SHFL(256, 2) SP_SHFL(256, 1)
#undef SP_SHFL
#undef SP_SMEM

    float inc = 0.0f;
    if (tid < 256) {
        inc = x;
        #pragma unroll
        for (int off = 1; off < 32; off <<= 1) {
            float v = __shfl_up_sync(0xffffffffu, inc, off);
            if (lane >= off) inc += v;
        }
        if (lane == 31) swsumf[tid >> 5] = inc;
    }
    __syncthreads();
    bool cond = false;
    if (tid < 256) {
        float pre = 0.0f;
        int w = tid >> 5;
        #pragma unroll
        for (int q = 0; q < 8; ++q) if (q < w) pre += swsumf[q];
        float cs = inc + pre;
        scs[tid] = cs;
        cond = (x - (cs - z) / (float)(tid + 1)) > 0.0f;
    }
    int rho = __syncthreads_count(cond ? 1 : 0);
    float theta = (scs[rho - 1] - z) / (float)rho;
    return fmaxf(wv - theta, 0.0f);
}

// ---------------------------------------------------------------------------
// u = L^T w (1024 threads; 8-way m-split, half2 columns).
// ---------------------------------------------------------------------------
__device__ __forceinline__ void compute_u_1024(
    int b, int tid, const float* sw, float* sbuf)
{
    const int q = tid >> 7, cp = tid & 127;
    const __half2* L2 = (const __half2*)(g_L16 + (size_t)b * NN * NN) + (size_t)(32 * q) * 128 + cp;
    float2 acc = make_float2(0.0f, 0.0f);
    #pragma unroll 8
    for (int m = 0; m < 32; ++m) {
        float2 f = __half22float2(__ldg(L2 + m * 128));
        float wm = sw[32 * q + m];
        acc.x += f.x * wm; acc.y += f.y * wm;
    }
    ((float2*)sbuf)[q * 128 + cp] = acc;
    __syncthreads();
    if (tid < 128) {
        float2 s = make_float2(0.0f, 0.0f);
        #pragma unroll
        for (int r = 0; r < 8; ++r) {
            float2 v = ((const float2*)sbuf)[r * 128 + tid];
            s.x += v.x; s.y += v.y;
        }
        ((float2*)(g_u + b * NN))[tid] = s;
    }
}

// ---------------------------------------------------------------------------
// Init kernel: w0 = proj(1/n), then u.
// ---------------------------------------------------------------------------
extern "C" __global__ void __launch_bounds__(1024)
init_kernel(const int* __restrict__ p_crisis)
{
    __shared__ float ssort[256], scs[256], sw[256];
    __shared__ float sbuf[2048];
    __shared__ float swsumf[8];

    const int b = blockIdx.x;
    const int tid = threadIdx.x;
    const int lane = tid & 31;
    const float crisis = (float)(*p_crisis);

    const float fl = (tid == BIL) ? 0.5f * crisis : 0.0f;
    const float z = 1.0f - 0.5f * crisis;
    float v = (1.0f / (float)NN) - fl;
    float pw = simplex_proj_fast(v, z, tid, lane, ssort, scs, swsumf) + fl;
    if (tid < 256) { g_w[b * NN + tid] = pw; sw[tid] = pw; }
    __syncthreads();
    compute_u_1024(b, tid, sw, sbuf);
}

// ---------------------------------------------------------------------------
// Loss partial-dot kernel (transposed eps stream).
// grid = NB*8: blk -> b=blk/8, chunk=(blk%8)/2 (64 n's), shalf=(blk%8)%2.
// Each active thread (tid<250) owns 4 scenarios (one uint2 per n), streams
// 64 n's with evict-first loads, writes fp32 partial dots.
// ---------------------------------------------------------------------------
extern "C" __global__ void __launch_bounds__(256)
loss_part_kernel()
{
    __shared__ float su[64];
    const int blk = blockIdx.x;
    const int b = blk >> 3;
    const int r = blk & 7;
    const int chunk = r >> 1;
    const int shalf = r & 1;
    const int tid = threadIdx.x;

    if (tid < 64) su[tid] = g_u[b * NN + chunk * 64 + tid];
    __syncthreads();
    if (tid >= 250) return;

    const int slot = shalf * 250 + tid;
    const __half* base = g_epsT + ((size_t)(b * NN + chunk * 64)) * NS + 4 * slot;

    float ax = 0.f, ay = 0.f, az = 0.f, aw = 0.f;
    #pragma unroll 8
    for (int n = 0; n < 64; ++n) {
        uint2 raw = __ldcs((const uint2*)(base + (size_t)n * NS));
        float un = su[n];
        float2 f0 = __half22float2(*(const __half2*)&raw.x);
        float2 f1 = __half22float2(*(const __half2*)&raw.y);
        ax += f0.x * un; ay += f0.y * un;
        az += f1.x * un; aw += f1.y * un;
    }
    float4 o = make_float4(ax, ay, az, aw);
    ((float4*)g_part)[((size_t)(chunk * NB + b) * NS) / 4 + slot] = o;
}

// ---------------------------------------------------------------------------
// Iteration kernel, 1024 threads per batch.
// ---------------------------------------------------------------------------
extern "C" __global__ void __launch_bounds__(1024)
iter_kernel(const float* __restrict__ mu,
            const int* __restrict__ p_crisis, const int* __restrict__ p_lambda,
            int t, float* __restrict__ out)
{
    __shared__ unsigned skey[NS];
    __shared__ int ssel[NS];
    __shared__ int shist[256];
    __shared__ float sbuf[2048];
    __shared__ float svv[256], sw[256], ssort[256], scs[256];
    __shared__ float swsumf[8];
    __shared__ int swsum[32];
    __shared__ unsigned s_P;
    __shared__ int s_k;

    const int b = blockIdx.x;
    const int tid = threadIdx.x;
    const int lane = tid & 31;
    const int warp = tid >> 5;

    // losses from partials -> monotone sortable keys (loss = -(sum partials))
    const float* p0 = g_part + (size_t)b * NS;
    const float* p1 = g_part + (size_t)(NB + b) * NS;
    const float* p2 = g_part + (size_t)(2 * NB + b) * NS;
    const float* p3 = g_part + (size_t)(3 * NB + b) * NS;
    for (int s = tid; s < NS; s += 1024) {
        float loss = -((p0[s] + p1[s]) + (p2[s] + p3[s]));
        unsigned ub = __float_as_uint(loss);
        skey[s] = (ub & 0x80000000u) ? ~ub : (ub | 0x80000000u);
    }
    if (tid == 0) { s_P = 0u; s_k = KK; }

    // 4-pass MSD radix select for the K-th largest key
    #pragma unroll
    for (int p = 0; p < 4; ++p) {
        const int shift = 24 - 8 * p;
        if (tid < 256) shist[tid] = 0;
        __syncthreads();
        const unsigned Pc = s_P;
        const int kcur = s_k;
        for (int s = tid; s < NS; s += 1024) {
            unsigned key = skey[s];
            bool match = (p == 0) || ((key >> (shift + 8)) == (Pc >> (shift + 8)));
            if (match) atomicAdd(&shist[(key >> shift) & 255u], 1);
        }
        __syncthreads();
        if (warp == 0) {
            int c[8]; int sum = 0;
            #pragma unroll
            for (int j = 0; j < 8; ++j) { c[j] = shist[255 - (lane * 8 + j)]; sum += c[j]; }
            int incs = sum;
            #pragma unroll
            for (int off = 1; off < 32; off <<= 1) {
                int v = __shfl_up_sync(0xffffffffu, incs, off);
                if (lane >= off) incs += v;
            }
            int run = incs - sum;
            #pragma unroll
            for (int j = 0; j < 8; ++j) {
                int C1 = run; run += c[j];
                if (run >= kcur && C1 < kcur) {
                    s_P = Pc | ((unsigned)(255 - (lane * 8 + j)) << shift);
                    s_k = kcur - C1;
                }
            }
        }
        __syncthreads();
    }
    const unsigned T = s_P;

    // deterministic compaction of selected scenarios
    bool m0 = skey[tid] >= T;
    bool m1 = (tid + 1024 < NS) && (skey[tid + 1024] >= T);
    int cnt = (int)m0 + (int)m1;
    {
        int incs = cnt;
        #pragma unroll
        for (int off = 1; off < 32; off <<= 1) {
            int v = __shfl_up_sync(0xffffffffu, incs, off);
            if (lane >= off) incs += v;
        }
        if (lane == 31) swsum[warp] = incs;
        __syncthreads();
        if (warp == 0) {
            int v = swsum[lane];
            #pragma unroll
            for (int off = 1; off < 32; off <<= 1) {
                int x = __shfl_up_sync(0xffffffffu, v, off);
                if (lane >= off) v += x;
            }
            swsum[lane] = v;
        }
        __syncthreads();
        int ofs = (incs - cnt) + (warp > 0 ? swsum[warp - 1] : 0);
        if (m0) ssel[ofs++] = tid;
        if (m1) ssel[ofs] = tid + 1024;
    }
    __syncthreads();
    const int total = swsum[31];
    const float coef = 1.0f / fmaxf((float)total, (float)KK);
    const float summ = (float)total * coef;

    // v accumulate over selected rows (row-major eps16), 8-way row split,
    // 2-way unrolled for MLP
    {
        const int grp = tid >> 7, cp = tid & 127;
        const __half2* e2 = (const __half2*)g_eps16 + (size_t)b * NS * 128;
        float2 acc = make_float2(0.0f, 0.0f);
        int i = grp;
        for (; i + 8 < total; i += 16) {
            float2 fa = __half22float2(__ldg(e2 + (size_t)ssel[i] * 128 + cp));
            float2 fb = __half22float2(__ldg(e2 + (size_t)ssel[i + 8] * 128 + cp));
            acc.x += fa.x + fb.x; acc.y += fa.y + fb.y;
        }
        if (i < total) {
            float2 fa = __half22float2(__ldg(e2 + (size_t)ssel[i] * 128 + cp));
            acc.x += fa.x; acc.y += fa.y;
        }
        ((float2*)sbuf)[grp * 128 + cp] = acc;
    }
    __syncthreads();
    if (tid < 128) {
        float2 s = make_float2(0.0f, 0.0f);
        #pragma unroll
        for (int r = 0; r < 8; ++r) {
            float2 v = ((const float2*)sbuf)[r * 128 + tid];
            s.x += v.x; s.y += v.y;
        }
        svv[2 * tid] = s.x * coef;
        svv[2 * tid + 1] = s.y * coef;
    }
    __syncthreads();

    // lv[n] = sum_m L[n][m] v[m] via LT16
    const int lam = *p_lambda;
    const float lamscale = (lam > 0) ? (1.0f + 1.0f / fmaxf((float)lam, 0.1f)) : 1.0f;
    {
        const int q = tid >> 7, cp = tid & 127;
        const __half2* LT2 = (const __half2*)(g_LT16 + (size_t)b * NN * NN) + (size_t)(32 * q) * 128 + cp;
        float2 acc = make_float2(0.0f, 0.0f);
        #pragma unroll 8
        for (int m = 0; m < 32; ++m) {
            float2 f = __half22float2(__ldg(LT2 + m * 128));
            float vm = svv[32 * q + m];
            acc.x += f.x * vm; acc.y += f.y * vm;
        }
        __syncthreads();
        ((float2*)sbuf)[q * 128 + cp] = acc;
    }
    __syncthreads();

    // projected update (threads < 256 own components)
    const float crisis = (float)(*p_crisis);
    const float z = 1.0f - 0.5f * crisis;
    const float lr = 0.5f / sqrtf((float)t + 1.0f);
    float wv = 0.0f, fl = 0.0f;
    if (tid < 256) {
        fl = (tid == BIL) ? 0.5f * crisis : 0.0f;
        const float mue = mu[b * NN + tid] * lamscale;
        const int cp = tid >> 1, sel = tid & 1;
        float lv = 0.0f;
        #pragma unroll
        for (int r = 0; r < 8; ++r) {
            float2 v = ((const float2*)sbuf)[r * 128 + cp];
            lv += sel ? v.y : v.x;
        }
        const float gval = -(summ * mue + lv);
        wv = g_w[b * NN + tid] - lr * gval - fl;
    }
    __syncthreads();
    float pw = simplex_proj_fast(wv, z, tid, lane, ssort, scs, swsumf) + fl;
    if (tid < 256) { g_w[b * NN + tid] = pw; sw[tid] = pw; }
    __syncthreads();

    if (t == NITERS - 1) {
        float wc = (tid < 256) ? fmaxf(pw, 0.0f) : 0.0f;
        float r = wc;
        if (tid < 256) {
            #pragma unroll
            for (int off = 16; off > 0; off >>= 1)
                r += __shfl_down_sync(0xffffffffu, r, off);
            if (lane == 0) swsumf[tid >> 5] = r;
        }
        __syncthreads();
        if (tid < 256) {
            float s = 0.0f;
            #pragma unroll
            for (int q = 0; q < 8; ++q) s += swsumf[q];
            out[b * NN + tid] = wc / (s + 1e-8f);
        }
    } else {
        compute_u_1024(b, tid, sw, sbuf);
    }
}

// ---------------------------------------------------------------------------
extern "C" void kernel_launch(void* const* d_in, const int* in_sizes, int n_in,
                              void* d_out, int out_size)
{
    const float* mu     = (const float*)d_in[0];
    const float* sigma  = (const float*)d_in[1];
    const float* eps    = (const float*)d_in[2];
    const int*   crisis = (const int*)d_in[3];
    const int*   lambda = (const int*)d_in[4];
    float* out = (float*)d_out;

    cudaFuncSetAttribute(chol_kernel, cudaFuncAttributeMaxDynamicSharedMemorySize,
                         32896 * sizeof(float));

    conv_kernel<<<16000, 256>>>(eps);
    transpose_kernel<<<NB * 256, 256>>>(eps);
    chol_kernel<<<NB, 256, 32896 * sizeof(float)>>>(sigma);
    init_kernel<<<NB, 1024>>>(crisis);
    for (int t = 0; t < NITERS; ++t) {
        loss_part_kernel<<<NB * 8, 256>>>();
        iter_kernel<<<NB, 1024>>>(mu, crisis, lambda, t, out);
    }
}

// round 5
// speedup vs baseline: 2.4817x; 1.1828x over previous
#include <cuda_runtime.h>
#include <cuda_fp16.h>
#include <math.h>

// Problem constants
#define NB 64
#define NN 256
#define NS 2000
#define KK 100
#define BIL 4
#define NITERS 200

// Device scratch
__device__ __align__(16) __half g_L16[(size_t)NB * NN * NN];   // 8.4MB  L[b][m][n]
__device__ __align__(16) __half g_LT16[(size_t)NB * NN * NN];  // 8.4MB  LT[b][m][n]=L[n][m]
__device__ __align__(16) __half g_eps16[(size_t)NB * NS * NN]; // 65.5MB row-major [b][s][n]
__device__ __align__(16) __half g_epsT[(size_t)NB * NN * NS];  // 65.5MB transposed [b][n][s]

// ---------------------------------------------------------------------------
// eps fp32 -> fp16 row-major (one thread per 8 elements)
// ---------------------------------------------------------------------------
extern "C" __global__ void __launch_bounds__(256)
conv_kernel(const float* __restrict__ eps)
{
    size_t gid = (size_t)blockIdx.x * blockDim.x + threadIdx.x;
    const size_t total8 = (size_t)NB * NS * NN / 8;
    if (gid >= total8) return;
    const float4* e4 = (const float4*)eps;
    float4 f0 = __ldcs(e4 + 2 * gid);
    float4 f1 = __ldcs(e4 + 2 * gid + 1);
    uint4 o;
    *(__half2*)&o.x = __floats2half2_rn(f0.x, f0.y);
    *(__half2*)&o.y = __floats2half2_rn(f0.z, f0.w);
    *(__half2*)&o.z = __floats2half2_rn(f1.x, f1.y);
    *(__half2*)&o.w = __floats2half2_rn(f1.z, f1.w);
    ((uint4*)g_eps16)[gid] = o;
}

// ---------------------------------------------------------------------------
// eps fp32 -> fp16 transposed [b][n][s], tiled 64(s) x 32(n)
// ---------------------------------------------------------------------------
extern "C" __global__ void __launch_bounds__(256)
transpose_kernel(const float* __restrict__ eps)
{
    __shared__ float tile[64][33];
    const int blk = blockIdx.x;
    const int b = blk >> 8;
    const int rest = blk & 255;
    const int st = rest >> 3;
    const int nt = rest & 7;
    const int s0 = st * 64, n0 = nt * 32;
    const int tid = threadIdx.x;

    #pragma unroll
    for (int k = 0; k < 8; ++k) {
        int idx = tid + 256 * k;
        int s = idx >> 5, n = idx & 31;
        float v = 0.0f;
        if (s0 + s < NS) v = __ldcs(&eps[((size_t)b * NS + s0 + s) * NN + n0 + n]);
        tile[s][n] = v;
    }
    __syncthreads();
    #pragma unroll
    for (int k = 0; k < 4; ++k) {
        int idx = tid + 256 * k;
        int n = idx >> 5, sp = idx & 31;
        int s = 2 * sp;
        if (s0 + s < NS) {
            __half2 h = __floats2half2_rn(tile[s][n], tile[s + 1][n]);
            *(__half2*)(g_epsT + ((size_t)b * NN + n0 + n) * NS + s0 + s) = h;
        }
    }
}

// ---------------------------------------------------------------------------
// Cholesky: one block per batch, packed lower triangle in smem; fp16 L, LT.
// ---------------------------------------------------------------------------
__device__ __forceinline__ int tri_row_of(int idx) {
    float f = sqrtf(8.0f * (float)idx + 1.0f);
    int i = (int)((f - 1.0f) * 0.5f);
    while ((i + 1) * (i + 2) / 2 <= idx) ++i;
    while (i * (i + 1) / 2 > idx) --i;
    return i;
}

extern "C" __global__ void __launch_bounds__(256)
chol_kernel(const float* __restrict__ sigma) {
    extern __shared__ float sm[];   // 32896 floats
    const int b = blockIdx.x;
    const int tid = threadIdx.x;
    const float* A = sigma + (size_t)b * NN * NN;

    for (int idx = tid; idx < 32896; idx += 256) {
        int i = tri_row_of(idx);
        int j = idx - i * (i + 1) / 2;
        float v = A[i * NN + j];
        if (i == j) v += 1e-4f;
        sm[idx] = v;
    }
    __syncthreads();

    __shared__ float sdiag;
    float acc = 0.0f;
    const int base_i = tid * (tid + 1) / 2;

    for (int j = 0; j < NN; ++j) {
        if (tid == j) {
            float d = sm[j * (j + 1) / 2 + j] - acc;
            sdiag = sqrtf(fmaxf(d, 1e-20f));
            sm[j * (j + 1) / 2 + j] = sdiag;
        }
        __syncthreads();
        float dinv = 1.0f / sdiag;
        if (tid > j) {
            const int base_j = j * (j + 1) / 2;
            float s = sm[base_i + j];
            int k = 0;
            for (; k + 4 <= j; k += 4) {
                s -= sm[base_i + k]     * sm[base_j + k];
                s -= sm[base_i + k + 1] * sm[base_j + k + 1];
                s -= sm[base_i + k + 2] * sm[base_j + k + 2];
                s -= sm[base_i + k + 3] * sm[base_j + k + 3];
            }
            for (; k < j; ++k) s -= sm[base_i + k] * sm[base_j + k];
            float lij = s * dinv;
            sm[base_i + j] = lij;
            acc += lij * lij;
        }
        __syncthreads();
    }

    __half* Lb  = g_L16  + (size_t)b * NN * NN;
    __half* LTb = g_LT16 + (size_t)b * NN * NN;
    for (int idx = tid; idx < NN * NN; idx += 256) {
        int i = idx >> 8, j = idx & 255;
        Lb[idx] = __float2half_rn((j <= i) ? sm[i * (i + 1) / 2 + j] : 0.0f);
    }
    for (int idx = tid; idx < NN * NN; idx += 256) {
        int r = idx >> 8, c = idx & 255;
        LTb[idx] = __float2half_rn((r <= c) ? sm[c * (c + 1) / 2 + r] : 0.0f);
    }
}

// ---------------------------------------------------------------------------
// Fast simplex projection (values on tid<256).
// ---------------------------------------------------------------------------
__device__ __forceinline__ float simplex_proj_fast(
    float wv, float z, int tid, int lane,
    float* ssort, float* scs, float* swsumf)
{
    float x = wv;

#define SP_SHFL(kk, jj) \
    if (tid < 256) { \
        float o = __shfl_xor_sync(0xffffffffu, x, (jj)); \
        bool keepMax = (((tid & (kk)) == 0) == ((tid & (jj)) == 0)); \
        x = keepMax ? fmaxf(x, o) : fminf(x, o); \
    }
#define SP_SMEM(kk, jj) { \
    if (tid < 256) ssort[tid] = x; \
    __syncthreads(); \
    if (tid < 256) { \
        float o = ssort[tid ^ (jj)]; \
        bool keepMax = (((tid & (kk)) == 0) == ((tid & (jj)) == 0)); \
        x = keepMax ? fmaxf(x, o) : fminf(x, o); \
    } \
    __syncthreads(); }

    SP_SHFL(2, 1)
    SP_SHFL(4, 2)  SP_SHFL(4, 1)
    SP_SHFL(8, 4)  SP_SHFL(8, 2)  SP_SHFL(8, 1)
    SP_SHFL(16, 8) SP_SHFL(16, 4) SP_SHFL(16, 2) SP_SHFL(16, 1)
    SP_SHFL(32, 16) SP_SHFL(32, 8) SP_SHFL(32, 4) SP_SHFL(32, 2) SP_SHFL(32, 1)
    SP_SMEM(64, 32)
    SP_SHFL(64, 16) SP_SHFL(64, 8) SP_SHFL(64, 4) SP_SHFL(64, 2) SP_SHFL(64, 1)
    SP_SMEM(128, 64) SP_SMEM(128, 32)
    SP_SHFL(128, 16) SP_SHFL(128, 8) SP_SHFL(128, 4) SP_SHFL(128, 2) SP_SHFL(128, 1)
    SP_SMEM(256, 128) SP_SMEM(256, 64) SP_SMEM(256, 32)
    SP_SHFL(256, 16) SP_SHFL(256, 8) SP_SHFL(256, 4) SP_SHFL(256, 2) SP_SHFL(256, 1)
#undef SP_SHFL
#undef SP_SMEM

    float inc = 0.0f;
    if (tid < 256) {
        inc = x;
        #pragma unroll
        for (int off = 1; off < 32; off <<= 1) {
            float v = __shfl_up_sync(0xffffffffu, inc, off);
            if (lane >= off) inc += v;
        }
        if (lane == 31) swsumf[tid >> 5] = inc;
    }
    __syncthreads();
    bool cond = false;
    if (tid < 256) {
        float pre = 0.0f;
        int w = tid >> 5;
        #pragma unroll
        for (int q = 0; q < 8; ++q) if (q < w) pre += swsumf[q];
        float cs = inc + pre;
        scs[tid] = cs;
        cond = (x - (cs - z) / (float)(tid + 1)) > 0.0f;
    }
    int rho = __syncthreads_count(cond ? 1 : 0);
    float theta = (scs[rho - 1] - z) / (float)rho;
    return fmaxf(wv - theta, 0.0f);
}

// ---------------------------------------------------------------------------
// u = L^T w into smem su (1024 threads; 8-way m-split, half2 columns).
// ---------------------------------------------------------------------------
__device__ __forceinline__ void compute_u_smem(
    int b, int tid, const float* sw, float* sbuf, float* su)
{
    const int q = tid >> 7, cp = tid & 127;
    const __half2* L2 = (const __half2*)(g_L16 + (size_t)b * NN * NN) + (size_t)(32 * q) * 128 + cp;
    float2 acc = make_float2(0.0f, 0.0f);
    #pragma unroll 8
    for (int m = 0; m < 32; ++m) {
        float2 f = __half22float2(__ldg(L2 + m * 128));
        float wm = sw[32 * q + m];
        acc.x += f.x * wm; acc.y += f.y * wm;
    }
    ((float2*)sbuf)[q * 128 + cp] = acc;
    __syncthreads();
    if (tid < 128) {
        float2 s = make_float2(0.0f, 0.0f);
        #pragma unroll
        for (int r = 0; r < 8; ++r) {
            float2 v = ((const float2*)sbuf)[r * 128 + tid];
            s.x += v.x; s.y += v.y;
        }
        su[2 * tid] = s.x;
        su[2 * tid + 1] = s.y;
    }
}

// ---------------------------------------------------------------------------
// Persistent solver: one block per batch runs all 200 iterations.
// Dynamic smem: 8000 floats (32KB): spart during loss phase, then aliased to
// ssel[2000] / sbuf[2048] / svv[256].
// ---------------------------------------------------------------------------
extern "C" __global__ void __launch_bounds__(1024, 1)
persist_kernel(const float* __restrict__ mu,
               const int* __restrict__ p_crisis, const int* __restrict__ p_lambda,
               float* __restrict__ out)
{
    extern __shared__ float dyn[];           // 8000 floats
    float* spart = dyn;                      // [4][2000] loss partials
    int*   ssel  = (int*)dyn;                // [2000]   (alias, after loss phase)
    float* sbuf  = dyn + 2048;               // [2048]
    float* svv   = dyn + 4352;               // [256]

    __shared__ float su[256], sw[256], ssort[256], scs[256];
    __shared__ unsigned skey[NS];
    __shared__ int shist[256];
    __shared__ float swsumf[8];
    __shared__ int swsum[32];
    __shared__ unsigned s_P;
    __shared__ int s_k;

    const int b = blockIdx.x;
    const int tid = threadIdx.x;
    const int lane = tid & 31;
    const int warp = tid >> 5;

    const float crisis = (float)(*p_crisis);
    const int lam = *p_lambda;
    const float lamscale = (lam > 0) ? (1.0f + 1.0f / fmaxf((float)lam, 0.1f)) : 1.0f;
    const float z = 1.0f - 0.5f * crisis;
    const float flme = (tid == BIL) ? 0.5f * crisis : 0.0f;
    float mue = 0.0f;
    if (tid < 256) mue = mu[b * NN + tid] * lamscale;

    // loss-phase thread mapping: nc in [0,4) owns 64 n's, sg in [0,250) owns 8 s's
    const int nc = tid / 250;
    const int sg = tid - nc * 250;
    const bool lactive = (tid < 1000);

    // ---- init: w0 = proj(uniform), u = L^T w0
    {
        float v = (1.0f / (float)NN) - flme;
        float pw = simplex_proj_fast(v, z, tid, lane, ssort, scs, swsumf) + flme;
        if (tid < 256) sw[tid] = pw;
        __syncthreads();
        compute_u_smem(b, tid, sw, sbuf, su);
        __syncthreads();
    }

    for (int t = 0; t < NITERS; ++t) {
        // ---- loss phase: spart[nc][8sg..8sg+8) = partial dots over 64 n's
        if (lactive) {
            const __half* base = g_epsT + ((size_t)(b * NN + nc * 64)) * NS + 8 * sg;
            float a0=0.f,a1=0.f,a2=0.f,a3=0.f,a4=0.f,a5=0.f,a6=0.f,a7=0.f;
            #pragma unroll 8
            for (int n = 0; n < 64; ++n) {
                uint4 raw = __ldcs((const uint4*)(base + (size_t)n * NS));
                float un = su[nc * 64 + n];
                float2 f0 = __half22float2(*(const __half2*)&raw.x);
                float2 f1 = __half22float2(*(const __half2*)&raw.y);
                float2 f2 = __half22float2(*(const __half2*)&raw.z);
                float2 f3 = __half22float2(*(const __half2*)&raw.w);
                a0 += f0.x * un; a1 += f0.y * un;
                a2 += f1.x * un; a3 += f1.y * un;
                a4 += f2.x * un; a5 += f2.y * un;
                a6 += f3.x * un; a7 += f3.y * un;
            }
            float* o = spart + nc * NS + 8 * sg;
            o[0]=a0; o[1]=a1; o[2]=a2; o[3]=a3; o[4]=a4; o[5]=a5; o[6]=a6; o[7]=a7;
        }
        __syncthreads();

        // losses -> monotone sortable keys (constant muw shift dropped: top-K invariant)
        for (int s = tid; s < NS; s += 1024) {
            float loss = -((spart[s] + spart[NS + s]) + (spart[2 * NS + s] + spart[3 * NS + s]));
            unsigned ub = __float_as_uint(loss);
            skey[s] = (ub & 0x80000000u) ? ~ub : (ub | 0x80000000u);
        }
        if (tid == 0) { s_P = 0u; s_k = KK; }
        __syncthreads();   // spart dead from here; aliases live

        // ---- 4-pass MSD radix select for K-th largest key
        #pragma unroll
        for (int p = 0; p < 4; ++p) {
            const int shift = 24 - 8 * p;
            if (tid < 256) shist[tid] = 0;
            __syncthreads();
            const unsigned Pc = s_P;
            const int kcur = s_k;
            for (int s = tid; s < NS; s += 1024) {
                unsigned key = skey[s];
                bool match = (p == 0) || ((key >> (shift + 8)) == (Pc >> (shift + 8)));
                if (match) atomicAdd(&shist[(key >> shift) & 255u], 1);
            }
            __syncthreads();
            if (warp == 0) {
                int c[8]; int sum = 0;
                #pragma unroll
                for (int j = 0; j < 8; ++j) { c[j] = shist[255 - (lane * 8 + j)]; sum += c[j]; }
                int incs = sum;
                #pragma unroll
                for (int off = 1; off < 32; off <<= 1) {
                    int v = __shfl_up_sync(0xffffffffu, incs, off);
                    if (lane >= off) incs += v;
                }
                int run = incs - sum;
                #pragma unroll
                for (int j = 0; j < 8; ++j) {
                    int C1 = run; run += c[j];
                    if (run >= kcur && C1 < kcur) {
                        s_P = Pc | ((unsigned)(255 - (lane * 8 + j)) << shift);
                        s_k = kcur - C1;
                    }
                }
            }
            __syncthreads();
        }
        const unsigned T = s_P;

        // ---- deterministic compaction of selected scenarios
        bool m0 = skey[tid] >= T;
        bool m1 = (tid + 1024 < NS) && (skey[tid + 1024] >= T);
        int cnt = (int)m0 + (int)m1;
        {
            int incs = cnt;
            #pragma unroll
            for (int off = 1; off < 32; off <<= 1) {
                int v = __shfl_up_sync(0xffffffffu, incs, off);
                if (lane >= off) incs += v;
            }
            if (lane == 31) swsum[warp] = incs;
            __syncthreads();
            if (warp == 0) {
                int v = swsum[lane];
                #pragma unroll
                for (int off = 1; off < 32; off <<= 1) {
                    int x = __shfl_up_sync(0xffffffffu, v, off);
                    if (lane >= off) v += x;
                }
                swsum[lane] = v;
            }
            __syncthreads();
            int ofs = (incs - cnt) + (warp > 0 ? swsum[warp - 1] : 0);
            if (m0) ssel[ofs++] = tid;
            if (m1) ssel[ofs] = tid + 1024;
        }
        __syncthreads();
        const int total = swsum[31];
        const float coef = 1.0f / fmaxf((float)total, (float)KK);
        const float summ = (float)total * coef;

        // ---- v = coef * sum_{selected s} eps16[b,s,:]  (8-way row split)
        {
            const int grp = tid >> 7, cp = tid & 127;
            const __half2* e2 = (const __half2*)g_eps16 + (size_t)b * NS * 128;
            float2 acc = make_float2(0.0f, 0.0f);
            int i = grp;
            for (; i + 8 < total; i += 16) {
                float2 fa = __half22float2(__ldg(e2 + (size_t)ssel[i] * 128 + cp));
                float2 fb = __half22float2(__ldg(e2 + (size_t)ssel[i + 8] * 128 + cp));
                acc.x += fa.x + fb.x; acc.y += fa.y + fb.y;
            }
            if (i < total) {
                float2 fa = __half22float2(__ldg(e2 + (size_t)ssel[i] * 128 + cp));
                acc.x += fa.x; acc.y += fa.y;
            }
            ((float2*)sbuf)[grp * 128 + cp] = acc;
        }
        __syncthreads();
        if (tid < 128) {
            float2 s = make_float2(0.0f, 0.0f);
            #pragma unroll
            for (int r = 0; r < 8; ++r) {
                float2 v = ((const float2*)sbuf)[r * 128 + tid];
                s.x += v.x; s.y += v.y;
            }
            svv[2 * tid] = s.x * coef;
            svv[2 * tid + 1] = s.y * coef;
        }
        __syncthreads();

        // ---- lv[n] = sum_m L[n][m] v[m] via LT16 (8-way m-split)
        {
            const int q = tid >> 7, cp = tid & 127;
            const __half2* LT2 = (const __half2*)(g_LT16 + (size_t)b * NN * NN) + (size_t)(32 * q) * 128 + cp;
            float2 acc = make_float2(0.0f, 0.0f);
            #pragma unroll 8
            for (int m = 0; m < 32; ++m) {
                float2 f = __half22float2(__ldg(LT2 + m * 128));
                float vm = svv[32 * q + m];
                acc.x += f.x * vm; acc.y += f.y * vm;
            }
            __syncthreads();
            ((float2*)sbuf)[q * 128 + cp] = acc;
        }
        __syncthreads();

        // ---- projected update (threads < 256 own components)
        const float lr = 0.5f / sqrtf((float)t + 1.0f);
        float wv = 0.0f;
        if (tid < 256) {
            const int cp = tid >> 1, sel = tid & 1;
            float lv = 0.0f;
            #pragma unroll
            for (int r = 0; r < 8; ++r) {
                float2 v = ((const float2*)sbuf)[r * 128 + cp];
                lv += sel ? v.y : v.x;
            }
            const float gval = -(summ * mue + lv);
            wv = sw[tid] - lr * gval - flme;
        }
        __syncthreads();
        float pw = simplex_proj_fast(wv, z, tid, lane, ssort, scs, swsumf) + flme;
        if (tid < 256) sw[tid] = pw;
        __syncthreads();

        if (t == NITERS - 1) {
            // ---- final clamp + renormalize
            float wc = (tid < 256) ? fmaxf(pw, 0.0f) : 0.0f;
            float r = wc;
            if (tid < 256) {
                #pragma unroll
                for (int off = 16; off > 0; off >>= 1)
                    r += __shfl_down_sync(0xffffffffu, r, off);
                if (lane == 0) swsumf[tid >> 5] = r;
            }
            __syncthreads();
            if (tid < 256) {
                float s = 0.0f;
                #pragma unroll
                for (int q = 0; q < 8; ++q) s += swsumf[q];
                out[b * NN + tid] = wc / (s + 1e-8f);
            }
        } else {
            compute_u_smem(b, tid, sw, sbuf, su);
            __syncthreads();   // su stable & dyn free before next loss phase
        }
    }
}

// ---------------------------------------------------------------------------
extern "C" void kernel_launch(void* const* d_in, const int* in_sizes, int n_in,
                              void* d_out, int out_size)
{
    const float* mu     = (const float*)d_in[0];
    const float* sigma  = (const float*)d_in[1];
    const float* eps    = (const float*)d_in[2];
    const int*   crisis = (const int*)d_in[3];
    const int*   lambda = (const int*)d_in[4];
    float* out = (float*)d_out;

    cudaFuncSetAttribute(chol_kernel, cudaFuncAttributeMaxDynamicSharedMemorySize,
                         32896 * sizeof(float));

    conv_kernel<<<16000, 256>>>(eps);
    transpose_kernel<<<NB * 256, 256>>>(eps);
    chol_kernel<<<NB, 256, 32896 * sizeof(float)>>>(sigma);
    persist_kernel<<<NB, 1024, 8000 * sizeof(float)>>>(mu, crisis, lambda, out);
}